// round 3
// baseline (speedup 1.0000x reference)
#include <cuda_runtime.h>
#include <math.h>

#define Vv 32000
#define Ee 128
#define Hh 256
#define Bb 64
#define TYy 64
#define TXx 128

// Scratch (device globals — no allocation allowed)
__device__ float g_hjproj[Bb * TXx * Hh];     // [b][tx][h]
__device__ float g_gi_emb[TYy * Bb * 768];    // emb-part of gi + b_ih, [t][b][j]
__device__ float g_S[TYy * Bb * 768];         // [t][b]{ s_i(256), c_new(512) }

__device__ __forceinline__ float sigmoidf_(float x) { return 1.f / (1.f + expf(-x)); }

// ---------------------------------------------------------------------------
// K1: gi_emb[t][b][j] = b_ih[j] + sum_k emb_eff[y[b,t]][k] * W_ih[j][k], k<128
// ---------------------------------------------------------------------------
__global__ __launch_bounds__(256) void emb_gemm_kernel(
    const int* __restrict__ y, const float* __restrict__ emb,
    const float* __restrict__ W_ih, const float* __restrict__ b_ih)
{
    __shared__ float Xs[16][128];
    const int tid = threadIdx.x;
    const int m_base = blockIdx.x * 16;

    for (int idx = tid; idx < 16 * 128; idx += 256) {
        int i = idx >> 7, k = idx & 127;
        int m = m_base + i;
        int tt = m >> 6, bb = m & 63;
        int yv = y[bb * TYy + tt];
        Xs[i][k] = (yv == 0) ? 0.f : emb[(size_t)yv * Ee + k];
    }
    __syncthreads();

    float acc0[16], acc1[16], acc2[16];
#pragma unroll
    for (int i = 0; i < 16; i++) { acc0[i] = 0.f; acc1[i] = 0.f; acc2[i] = 0.f; }

    const float* w0 = W_ih + (size_t)tid * 640;
    const float* w1 = W_ih + (size_t)(tid + 256) * 640;
    const float* w2 = W_ih + (size_t)(tid + 512) * 640;

    for (int k = 0; k < 128; k++) {
        float a = w0[k], b = w1[k], c = w2[k];
#pragma unroll
        for (int i = 0; i < 16; i++) {
            float x = Xs[i][k];
            acc0[i] = fmaf(x, a, acc0[i]);
            acc1[i] = fmaf(x, b, acc1[i]);
            acc2[i] = fmaf(x, c, acc2[i]);
        }
    }
    float bi0 = b_ih[tid], bi1 = b_ih[tid + 256], bi2 = b_ih[tid + 512];
#pragma unroll
    for (int i = 0; i < 16; i++) {
        size_t base = (size_t)(m_base + i) * 768;
        g_gi_emb[base + tid]       = acc0[i] + bi0;
        g_gi_emb[base + tid + 256] = acc1[i] + bi1;
        g_gi_emb[base + tid + 512] = acc2[i] + bi2;
    }
}

// ---------------------------------------------------------------------------
// K2: one step of the recurrence. grid = 64 blocks (one per batch), 256 thr.
// ---------------------------------------------------------------------------
__global__ __launch_bounds__(256) void step_kernel(
    int t,
    const float* __restrict__ h_j, const float* __restrict__ W_ih,
    const float* __restrict__ W_hh, const float* __restrict__ b_hh,
    const float* __restrict__ W_a, const float* __restrict__ v_a)
{
    const int b = blockIdx.x;
    const int tid = threadIdx.x;

    __shared__ float hi_s[256];
    __shared__ float ci_s[512];
    __shared__ float si_s[256];
    __shared__ float sp_s[256];
    __shared__ float e_s[128];
    __shared__ float red_s[128];
    __shared__ float va_s[256];

    if (t == 0) {
        hi_s[tid] = 0.f;
        ci_s[tid] = 0.f;
        ci_s[tid + 256] = 0.f;
    } else {
        const float* Sprev = g_S + ((size_t)(t - 1) * Bb + b) * 768;
        hi_s[tid] = Sprev[tid];
        ci_s[tid] = Sprev[256 + tid];
        ci_s[tid + 256] = Sprev[512 + tid];
    }
    va_s[tid] = v_a[tid];
    __syncthreads();

    // --- gates: thread tid -> rows tid (r), tid+256 (z), tid+512 (n) ---
    size_t gbase = ((size_t)t * Bb + b) * 768;
    float gi0 = g_gi_emb[gbase + tid];
    float gi1 = g_gi_emb[gbase + tid + 256];
    float gi2 = g_gi_emb[gbase + tid + 512];

    float a0 = 0.f, a1 = 0.f, a2 = 0.f;
    {
        const float4* w0p = (const float4*)(W_ih + (size_t)tid * 640 + 128);
        const float4* w1p = (const float4*)(W_ih + (size_t)(tid + 256) * 640 + 128);
        const float4* w2p = (const float4*)(W_ih + (size_t)(tid + 512) * 640 + 128);
        const float4* cp  = (const float4*)ci_s;
#pragma unroll 4
        for (int k4 = 0; k4 < 128; k4++) {
            float4 c = cp[k4];
            float4 w = w0p[k4];
            a0 += c.x * w.x + c.y * w.y + c.z * w.z + c.w * w.w;
            w = w1p[k4];
            a1 += c.x * w.x + c.y * w.y + c.z * w.z + c.w * w.w;
            w = w2p[k4];
            a2 += c.x * w.x + c.y * w.y + c.z * w.z + c.w * w.w;
        }
    }
    float h0 = 0.f, h1 = 0.f, h2 = 0.f;
    {
        const float4* v0p = (const float4*)(W_hh + (size_t)tid * 256);
        const float4* v1p = (const float4*)(W_hh + (size_t)(tid + 256) * 256);
        const float4* v2p = (const float4*)(W_hh + (size_t)(tid + 512) * 256);
        const float4* hp  = (const float4*)hi_s;
#pragma unroll 4
        for (int k4 = 0; k4 < 64; k4++) {
            float4 h = hp[k4];
            float4 w = v0p[k4];
            h0 += h.x * w.x + h.y * w.y + h.z * w.z + h.w * w.w;
            w = v1p[k4];
            h1 += h.x * w.x + h.y * w.y + h.z * w.z + h.w * w.w;
            w = v2p[k4];
            h2 += h.x * w.x + h.y * w.y + h.z * w.z + h.w * w.w;
        }
    }
    float ghr = h0 + b_hh[tid];
    float ghz = h1 + b_hh[tid + 256];
    float ghn = h2 + b_hh[tid + 512];

    // FIX: include the c_i @ W_ih part (a0/a1/a2) in the gate inputs.
    float r = sigmoidf_(gi0 + a0 + ghr);
    float z = sigmoidf_(gi1 + a1 + ghz);
    float n = tanhf(gi2 + a2 + r * ghn);
    float hprev = hi_s[tid];
    float s = (1.f - z) * n + z * hprev;

    si_s[tid] = s;
    g_S[gbase + tid] = s;
    __syncthreads();

    // --- s_proj[h] = sum_k s_i[k] * W_a[h][k] (k < 256) ---
    {
        float sp = 0.f;
        const float4* wa = (const float4*)(W_a + (size_t)tid * 768);
        const float4* sip = (const float4*)si_s;
#pragma unroll 8
        for (int k4 = 0; k4 < 64; k4++) {
            float4 sv = sip[k4];
            float4 w = wa[k4];
            sp += sv.x * w.x + sv.y * w.y + sv.z * w.z + sv.w * w.w;
        }
        sp_s[tid] = sp;
    }
    __syncthreads();

    // --- energy over TX=128 (first 128 threads) ---
    if (tid < 128) {
        const float* hp = g_hjproj + ((size_t)b * TXx + tid) * Hh;
        float e = 0.f;
#pragma unroll 4
        for (int h = 0; h < 256; h++)
            e += tanhf(sp_s[h] + hp[h]) * va_s[h];
        e_s[tid] = e;
        red_s[tid] = e;
    }
    __syncthreads();
    for (int st = 64; st > 0; st >>= 1) {
        if (tid < st) red_s[tid] = fmaxf(red_s[tid], red_s[tid + st]);
        __syncthreads();
    }
    float mx = red_s[0];
    __syncthreads();
    if (tid < 128) {
        float ex = expf(e_s[tid] - mx);
        e_s[tid] = ex;
        red_s[tid] = ex;
    }
    __syncthreads();
    for (int st = 64; st > 0; st >>= 1) {
        if (tid < st) red_s[tid] += red_s[tid + st];
        __syncthreads();
    }
    float inv = 1.f / red_s[0];
    __syncthreads();
    if (tid < 128) e_s[tid] *= inv;
    __syncthreads();

    // --- c_new[k] = sum_t' alpha[t'] * h_j[b][t'][k] ---
    float c0 = 0.f, c1 = 0.f;
    const float* hjb = h_j + (size_t)b * TXx * 512;
#pragma unroll 4
    for (int tp = 0; tp < 128; tp++) {
        float al = e_s[tp];
        c0 = fmaf(al, hjb[(size_t)tp * 512 + tid], c0);
        c1 = fmaf(al, hjb[(size_t)tp * 512 + 256 + tid], c1);
    }
    g_S[gbase + 256 + tid] = c0;
    g_S[gbase + 512 + tid] = c1;
}

// ---------------------------------------------------------------------------
// SGEMM C = A * B^T, A: MxK row-major, B rows K-contiguous (ldb).
// MODE 0: plain C[m*N+n].
// MODE 1: column j maps to W_mo row (j&1)*V + (j>>1); epilogue does
//         out[b][t][p] = max(acc_even + bias[p], acc_odd + bias[V+p]).
// 128x128x16 tiles, 256 threads, 8x8 per thread, double-buffered smem.
// ---------------------------------------------------------------------------
template <int MODE>
__global__ __launch_bounds__(256) void sgemm_nt(
    int M, int N, int K,
    const float* __restrict__ A, int lda,
    const float* __restrict__ B, int ldb,
    float* __restrict__ C,
    const float* __restrict__ bias)
{
    constexpr int BM = 128, BN = 128, BK = 16;
    __shared__ float As[2][BK][BM];
    __shared__ float Bs[2][BK][BN];

    const int tid = threadIdx.x;
    const int m0 = blockIdx.x * BM;
    const int n0 = blockIdx.y * BN;
    const int tx = tid & 15;
    const int ty = tid >> 4;

    const int lRow = tid >> 1;        // 0..127
    const int lK = (tid & 1) * 8;     // 0 or 8

    const float* Aptr = A + (size_t)(m0 + lRow) * lda + lK;
    int nIdx = n0 + lRow;
    int gr = (MODE == 1) ? ((nIdx & 1) * Vv + (nIdx >> 1)) : nIdx;
    const float* Bptr = B + (size_t)gr * ldb + lK;

    float acc[8][8];
#pragma unroll
    for (int i = 0; i < 8; i++)
#pragma unroll
        for (int j = 0; j < 8; j++) acc[i][j] = 0.f;

    const int nk = K / BK;

    float4 ar0, ar1, br0, br1;
    ar0 = *(const float4*)(Aptr);
    ar1 = *(const float4*)(Aptr + 4);
    br0 = *(const float4*)(Bptr);
    br1 = *(const float4*)(Bptr + 4);
#pragma unroll
    for (int q = 0; q < 4; q++) {
        As[0][lK + q][lRow] = ((const float*)&ar0)[q];
        As[0][lK + 4 + q][lRow] = ((const float*)&ar1)[q];
        Bs[0][lK + q][lRow] = ((const float*)&br0)[q];
        Bs[0][lK + 4 + q][lRow] = ((const float*)&br1)[q];
    }
    __syncthreads();

    for (int kt = 0; kt < nk; kt++) {
        const int cur = kt & 1;
        const bool has_next = (kt + 1 < nk);
        if (has_next) {
            const float* Ap = Aptr + (kt + 1) * BK;
            const float* Bp = Bptr + (kt + 1) * BK;
            ar0 = *(const float4*)(Ap);
            ar1 = *(const float4*)(Ap + 4);
            br0 = *(const float4*)(Bp);
            br1 = *(const float4*)(Bp + 4);
        }
#pragma unroll
        for (int kk = 0; kk < BK; kk++) {
            float4 a0 = *(const float4*)&As[cur][kk][ty * 8];
            float4 a1 = *(const float4*)&As[cur][kk][ty * 8 + 4];
            float4 b0 = *(const float4*)&Bs[cur][kk][tx * 8];
            float4 b1 = *(const float4*)&Bs[cur][kk][tx * 8 + 4];
            float av[8] = {a0.x, a0.y, a0.z, a0.w, a1.x, a1.y, a1.z, a1.w};
            float bv[8] = {b0.x, b0.y, b0.z, b0.w, b1.x, b1.y, b1.z, b1.w};
#pragma unroll
            for (int i = 0; i < 8; i++)
#pragma unroll
                for (int j = 0; j < 8; j++)
                    acc[i][j] = fmaf(av[i], bv[j], acc[i][j]);
        }
        if (has_next) {
            const int nxt = cur ^ 1;
#pragma unroll
            for (int q = 0; q < 4; q++) {
                As[nxt][lK + q][lRow] = ((const float*)&ar0)[q];
                As[nxt][lK + 4 + q][lRow] = ((const float*)&ar1)[q];
                Bs[nxt][lK + q][lRow] = ((const float*)&br0)[q];
                Bs[nxt][lK + 4 + q][lRow] = ((const float*)&br1)[q];
            }
            __syncthreads();
        }
    }

    if (MODE == 0) {
#pragma unroll
        for (int i = 0; i < 8; i++) {
            float* crow = C + (size_t)(m0 + ty * 8 + i) * N + n0 + tx * 8;
            float4 v0 = {acc[i][0], acc[i][1], acc[i][2], acc[i][3]};
            float4 v1 = {acc[i][4], acc[i][5], acc[i][6], acc[i][7]};
            *(float4*)(crow) = v0;
            *(float4*)(crow + 4) = v1;
        }
    } else {
#pragma unroll
        for (int i = 0; i < 8; i++) {
            int m = m0 + ty * 8 + i;
            int tt = m >> 6, bb = m & 63;
            float* orow = C + (size_t)bb * (TYy * Vv) + (size_t)tt * Vv;
#pragma unroll
            for (int j = 0; j < 8; j += 2) {
                int col = n0 + tx * 8 + j;
                int p = col >> 1;
                float v0 = acc[i][j] + bias[p];
                float v1 = acc[i][j + 1] + bias[Vv + p];
                orow[p] = fmaxf(v0, v1);
            }
        }
    }
}

// ---------------------------------------------------------------------------
extern "C" void kernel_launch(void* const* d_in, const int* in_sizes, int n_in,
                              void* d_out, int out_size)
{
    const int*   y    = (const int*)d_in[0];
    const float* h_j  = (const float*)d_in[1];
    const float* emb  = (const float*)d_in[2];
    const float* W_ih = (const float*)d_in[3];
    const float* W_hh = (const float*)d_in[4];
    const float* b_ih = (const float*)d_in[5];
    const float* b_hh = (const float*)d_in[6];
    const float* W_a  = (const float*)d_in[7];
    const float* v_a  = (const float*)d_in[8];
    const float* W_mo = (const float*)d_in[9];
    const float* b_mo = (const float*)d_in[10];
    float* out = (float*)d_out;

    void* hjp_v; cudaGetSymbolAddress(&hjp_v, g_hjproj);
    float* hjp = (float*)hjp_v;
    void* S_v;   cudaGetSymbolAddress(&S_v, g_S);
    float* S = (float*)S_v;

    // hj_proj: (B*TX, 512) @ (512, 256)  with B rows = W_a[:, 256:768]
    sgemm_nt<0><<<dim3((Bb * TXx) / 128, Hh / 128), 256>>>(
        Bb * TXx, Hh, 2 * Hh, h_j, 2 * Hh, W_a + Hh, 3 * Hh, hjp, nullptr);

    // emb-side of gi (+ b_ih), with emb row 0 zeroed
    emb_gemm_kernel<<<(TYy * Bb) / 16, 256>>>(y, emb, W_ih, b_ih);

    // sequential recurrence
    for (int t = 0; t < TYy; t++)
        step_kernel<<<Bb, 256>>>(t, h_j, W_ih, W_hh, b_hh, W_a, v_a);

    // deferred output projection with fused pair-max + bias epilogue
    sgemm_nt<1><<<dim3((TYy * Bb) / 128, (2 * Vv) / 128), 256>>>(
        TYy * Bb, 2 * Vv, 3 * Hh, S, 3 * Hh, W_mo, 3 * Hh, out, b_mo);
}

// round 7
// speedup vs baseline: 1.5624x; 1.5624x over previous
#include <cuda_runtime.h>
#include <cuda_bf16.h>
#include <math.h>
#include <stdint.h>

#define Vv 32000
#define Ee 128
#define Hh 256
#define Bb 64
#define TYy 64
#define TXx 128

#define NKB 36             // K-blocks of 64 bf16 (K_eff = 3*768 = 2304)
#define KTILE_BYTES 16384  // 128 rows x 64 bf16 (swizzled)
#define STAGE_BYTES 32768  // A tile + B tile
#define NSTAGE 3

// Scratch (device globals — no allocation allowed)
__device__ float g_hjproj[Bb * TXx * Hh];
__device__ float g_gi_emb[TYy * Bb * 768];
__device__ float g_S[TYy * Bb * 768];   // [t][b]{ s_i(256), c_new(512) }
// bf16-split tiled operands for the big GEMM (pre-swizzled 128x64 tiles)
__device__ __align__(128) unsigned short g_A2[32 * NKB * 8192];    // 32 m-tiles
__device__ __align__(128) unsigned short g_B2[500 * NKB * 8192];   // 500 n-tiles

__device__ __forceinline__ float sigmoidf_(float x) { return 1.f / (1.f + expf(-x)); }
__device__ __forceinline__ float tanh_fast(float x) {
    float y; asm("tanh.approx.f32 %0, %1;" : "=f"(y) : "f"(x)); return y;
}
__device__ __forceinline__ uint32_t smem_u32(const void* p) {
    uint32_t a;
    asm("{ .reg .u64 t; cvta.to.shared.u64 t, %1; cvt.u32.u64 %0, t; }" : "=r"(a) : "l"(p));
    return a;
}
__device__ __forceinline__ uint32_t sw128(uint32_t off) { return off ^ ((off >> 3) & 0x70); }

__device__ __forceinline__ void cp_async16(uint32_t saddr, const void* g) {
    asm volatile("cp.async.cg.shared.global [%0], [%1], 16;" :: "r"(saddr), "l"(g));
}
__device__ __forceinline__ void cp_commit() { asm volatile("cp.async.commit_group;"); }

__device__ __forceinline__ void ldsm4(uint32_t* r, uint32_t addr) {
    asm volatile("ldmatrix.sync.aligned.m8n8.x4.shared.b16 {%0,%1,%2,%3}, [%4];"
                 : "=r"(r[0]), "=r"(r[1]), "=r"(r[2]), "=r"(r[3]) : "r"(addr));
}
__device__ __forceinline__ void mma16816(float* d, const uint32_t* a, uint32_t b0, uint32_t b1) {
    asm volatile("mma.sync.aligned.m16n8k16.row.col.f32.bf16.bf16.f32 "
                 "{%0,%1,%2,%3}, {%4,%5,%6,%7}, {%8,%9}, {%0,%1,%2,%3};"
                 : "+f"(d[0]), "+f"(d[1]), "+f"(d[2]), "+f"(d[3])
                 : "r"(a[0]), "r"(a[1]), "r"(a[2]), "r"(a[3]), "r"(b0), "r"(b1));
}

// ---------------------------------------------------------------------------
// K1: gi_emb = b_ih + emb_eff[y] @ W_ih[:, :128].T
// ---------------------------------------------------------------------------
__global__ __launch_bounds__(256) void emb_gemm_kernel(
    const int* __restrict__ y, const float* __restrict__ emb,
    const float* __restrict__ W_ih, const float* __restrict__ b_ih)
{
    __shared__ float Xs[16][128];
    const int tid = threadIdx.x;
    const int m_base = blockIdx.x * 16;

    for (int idx = tid; idx < 16 * 128; idx += 256) {
        int i = idx >> 7, k = idx & 127;
        int m = m_base + i;
        int tt = m >> 6, bb = m & 63;
        int yv = y[bb * TYy + tt];
        Xs[i][k] = (yv == 0) ? 0.f : emb[(size_t)yv * Ee + k];
    }
    __syncthreads();

    float acc0[16], acc1[16], acc2[16];
#pragma unroll
    for (int i = 0; i < 16; i++) { acc0[i] = 0.f; acc1[i] = 0.f; acc2[i] = 0.f; }

    const float* w0 = W_ih + (size_t)tid * 640;
    const float* w1 = W_ih + (size_t)(tid + 256) * 640;
    const float* w2 = W_ih + (size_t)(tid + 512) * 640;

    for (int k = 0; k < 128; k++) {
        float a = w0[k], b = w1[k], c = w2[k];
#pragma unroll
        for (int i = 0; i < 16; i++) {
            float x = Xs[i][k];
            acc0[i] = fmaf(x, a, acc0[i]);
            acc1[i] = fmaf(x, b, acc1[i]);
            acc2[i] = fmaf(x, c, acc2[i]);
        }
    }
    float bi0 = b_ih[tid], bi1 = b_ih[tid + 256], bi2 = b_ih[tid + 512];
#pragma unroll
    for (int i = 0; i < 16; i++) {
        size_t base = (size_t)(m_base + i) * 768;
        g_gi_emb[base + tid]       = acc0[i] + bi0;
        g_gi_emb[base + tid + 256] = acc1[i] + bi1;
        g_gi_emb[base + tid + 512] = acc2[i] + bi2;
    }
}

// ---------------------------------------------------------------------------
// K2: one recurrence step (64 blocks = batch, 256 threads)
// ---------------------------------------------------------------------------
__global__ __launch_bounds__(256) void step_kernel(
    int t,
    const float* __restrict__ h_j, const float* __restrict__ W_ih,
    const float* __restrict__ W_hh, const float* __restrict__ b_hh,
    const float* __restrict__ W_a, const float* __restrict__ v_a)
{
    const int b = blockIdx.x;
    const int tid = threadIdx.x;

    __shared__ float hi_s[256];
    __shared__ float ci_s[512];
    __shared__ float si_s[256];
    __shared__ float sp_s[256];
    __shared__ float e_s[128];
    __shared__ float red_s[128];
    __shared__ float va_s[256];

    if (t == 0) {
        hi_s[tid] = 0.f;
        ci_s[tid] = 0.f;
        ci_s[tid + 256] = 0.f;
    } else {
        const float* Sprev = g_S + ((size_t)(t - 1) * Bb + b) * 768;
        hi_s[tid] = Sprev[tid];
        ci_s[tid] = Sprev[256 + tid];
        ci_s[tid + 256] = Sprev[512 + tid];
    }
    va_s[tid] = v_a[tid];
    __syncthreads();

    size_t gbase = ((size_t)t * Bb + b) * 768;
    float gi0 = g_gi_emb[gbase + tid];
    float gi1 = g_gi_emb[gbase + tid + 256];
    float gi2 = g_gi_emb[gbase + tid + 512];

    float a0 = 0.f, a1 = 0.f, a2 = 0.f;
    {
        const float4* w0p = (const float4*)(W_ih + (size_t)tid * 640 + 128);
        const float4* w1p = (const float4*)(W_ih + (size_t)(tid + 256) * 640 + 128);
        const float4* w2p = (const float4*)(W_ih + (size_t)(tid + 512) * 640 + 128);
        const float4* cp  = (const float4*)ci_s;
#pragma unroll 4
        for (int k4 = 0; k4 < 128; k4++) {
            float4 c = cp[k4];
            float4 w = w0p[k4];
            a0 += c.x * w.x + c.y * w.y + c.z * w.z + c.w * w.w;
            w = w1p[k4];
            a1 += c.x * w.x + c.y * w.y + c.z * w.z + c.w * w.w;
            w = w2p[k4];
            a2 += c.x * w.x + c.y * w.y + c.z * w.z + c.w * w.w;
        }
    }
    float h0 = 0.f, h1 = 0.f, h2 = 0.f;
    {
        const float4* v0p = (const float4*)(W_hh + (size_t)tid * 256);
        const float4* v1p = (const float4*)(W_hh + (size_t)(tid + 256) * 256);
        const float4* v2p = (const float4*)(W_hh + (size_t)(tid + 512) * 256);
        const float4* hp  = (const float4*)hi_s;
#pragma unroll 4
        for (int k4 = 0; k4 < 64; k4++) {
            float4 h = hp[k4];
            float4 w = v0p[k4];
            h0 += h.x * w.x + h.y * w.y + h.z * w.z + h.w * w.w;
            w = v1p[k4];
            h1 += h.x * w.x + h.y * w.y + h.z * w.z + h.w * w.w;
            w = v2p[k4];
            h2 += h.x * w.x + h.y * w.y + h.z * w.z + h.w * w.w;
        }
    }
    float ghr = h0 + b_hh[tid];
    float ghz = h1 + b_hh[tid + 256];
    float ghn = h2 + b_hh[tid + 512];

    float r = sigmoidf_(gi0 + a0 + ghr);
    float z = sigmoidf_(gi1 + a1 + ghz);
    float n = tanhf(gi2 + a2 + r * ghn);
    float hprev = hi_s[tid];
    float s = (1.f - z) * n + z * hprev;

    si_s[tid] = s;
    g_S[gbase + tid] = s;
    __syncthreads();

    {
        float sp = 0.f;
        const float4* wa = (const float4*)(W_a + (size_t)tid * 768);
        const float4* sip = (const float4*)si_s;
#pragma unroll 8
        for (int k4 = 0; k4 < 64; k4++) {
            float4 sv = sip[k4];
            float4 w = wa[k4];
            sp += sv.x * w.x + sv.y * w.y + sv.z * w.z + sv.w * w.w;
        }
        sp_s[tid] = sp;
    }
    __syncthreads();

    if (tid < 128) {
        const float* hp = g_hjproj + ((size_t)b * TXx + tid) * Hh;
        float e = 0.f;
#pragma unroll 4
        for (int h = 0; h < 256; h++)
            e += tanh_fast(sp_s[h] + hp[h]) * va_s[h];
        e_s[tid] = e;
        red_s[tid] = e;
    }
    __syncthreads();
    for (int st = 64; st > 0; st >>= 1) {
        if (tid < st) red_s[tid] = fmaxf(red_s[tid], red_s[tid + st]);
        __syncthreads();
    }
    float mx = red_s[0];
    __syncthreads();
    if (tid < 128) {
        float ex = expf(e_s[tid] - mx);
        e_s[tid] = ex;
        red_s[tid] = ex;
    }
    __syncthreads();
    for (int st = 64; st > 0; st >>= 1) {
        if (tid < st) red_s[tid] += red_s[tid + st];
        __syncthreads();
    }
    float inv = 1.f / red_s[0];
    __syncthreads();
    if (tid < 128) e_s[tid] *= inv;
    __syncthreads();

    float c0 = 0.f, c1 = 0.f;
    const float* hjb = h_j + (size_t)b * TXx * 512;
#pragma unroll 4
    for (int tp = 0; tp < 128; tp++) {
        float al = e_s[tp];
        c0 = fmaf(al, hjb[(size_t)tp * 512 + tid], c0);
        c1 = fmaf(al, hjb[(size_t)tp * 512 + 256 + tid], c1);
    }
    g_S[gbase + 256 + tid] = c0;
    g_S[gbase + 512 + tid] = c1;
}

// ---------------------------------------------------------------------------
// fp32 SIMT SGEMM (only for hj_proj)
// ---------------------------------------------------------------------------
__global__ __launch_bounds__(256) void sgemm_nt(
    int M, int N, int K,
    const float* __restrict__ A, int lda,
    const float* __restrict__ B, int ldb,
    float* __restrict__ C)
{
    constexpr int BMs = 128, BNs = 128, BKs = 16;
    __shared__ float As[2][BKs][BMs];
    __shared__ float Bs[2][BKs][BNs];

    const int tid = threadIdx.x;
    const int m0 = blockIdx.x * BMs;
    const int n0 = blockIdx.y * BNs;
    const int tx = tid & 15;
    const int ty = tid >> 4;
    const int lRow = tid >> 1;
    const int lK = (tid & 1) * 8;

    const float* Aptr = A + (size_t)(m0 + lRow) * lda + lK;
    const float* Bptr = B + (size_t)(n0 + lRow) * ldb + lK;

    float acc[8][8];
#pragma unroll
    for (int i = 0; i < 8; i++)
#pragma unroll
        for (int j = 0; j < 8; j++) acc[i][j] = 0.f;

    const int nk = K / BKs;
    float4 ar0, ar1, br0, br1;
    ar0 = *(const float4*)(Aptr);
    ar1 = *(const float4*)(Aptr + 4);
    br0 = *(const float4*)(Bptr);
    br1 = *(const float4*)(Bptr + 4);
#pragma unroll
    for (int q = 0; q < 4; q++) {
        As[0][lK + q][lRow] = ((const float*)&ar0)[q];
        As[0][lK + 4 + q][lRow] = ((const float*)&ar1)[q];
        Bs[0][lK + q][lRow] = ((const float*)&br0)[q];
        Bs[0][lK + 4 + q][lRow] = ((const float*)&br1)[q];
    }
    __syncthreads();

    for (int kt = 0; kt < nk; kt++) {
        const int cur = kt & 1;
        const bool has_next = (kt + 1 < nk);
        if (has_next) {
            const float* Ap = Aptr + (kt + 1) * BKs;
            const float* Bp = Bptr + (kt + 1) * BKs;
            ar0 = *(const float4*)(Ap);
            ar1 = *(const float4*)(Ap + 4);
            br0 = *(const float4*)(Bp);
            br1 = *(const float4*)(Bp + 4);
        }
#pragma unroll
        for (int kk = 0; kk < BKs; kk++) {
            float4 a0 = *(const float4*)&As[cur][kk][ty * 8];
            float4 a1 = *(const float4*)&As[cur][kk][ty * 8 + 4];
            float4 b0 = *(const float4*)&Bs[cur][kk][tx * 8];
            float4 b1 = *(const float4*)&Bs[cur][kk][tx * 8 + 4];
            float av[8] = {a0.x, a0.y, a0.z, a0.w, a1.x, a1.y, a1.z, a1.w};
            float bv[8] = {b0.x, b0.y, b0.z, b0.w, b1.x, b1.y, b1.z, b1.w};
#pragma unroll
            for (int i = 0; i < 8; i++)
#pragma unroll
                for (int j = 0; j < 8; j++)
                    acc[i][j] = fmaf(av[i], bv[j], acc[i][j]);
        }
        if (has_next) {
            const int nxt = cur ^ 1;
#pragma unroll
            for (int q = 0; q < 4; q++) {
                As[nxt][lK + q][lRow] = ((const float*)&ar0)[q];
                As[nxt][lK + 4 + q][lRow] = ((const float*)&ar1)[q];
                Bs[nxt][lK + q][lRow] = ((const float*)&br0)[q];
                Bs[nxt][lK + 4 + q][lRow] = ((const float*)&br1)[q];
            }
            __syncthreads();
        }
    }
#pragma unroll
    for (int i = 0; i < 8; i++) {
        float* crow = C + (size_t)(m0 + ty * 8 + i) * N + n0 + tx * 8;
        float4 v0 = {acc[i][0], acc[i][1], acc[i][2], acc[i][3]};
        float4 v1 = {acc[i][4], acc[i][5], acc[i][6], acc[i][7]};
        *(float4*)(crow) = v0;
        *(float4*)(crow + 4) = v1;
    }
}

// ---------------------------------------------------------------------------
// conv_W: W_mo (fp32, interleave-reordered rows) -> g_B2 bf16 split tiles.
// 128 rows per tile. Terms along K: 0 = hi, 1 = lo, 2 = hi.
// ---------------------------------------------------------------------------
__global__ __launch_bounds__(128) void conv_W_kernel(const float* __restrict__ W_mo)
{
    const int kb = blockIdx.x, nt = blockIdx.y;
    const int r = threadIdx.x;                  // 0..127
    const int n = nt * 128 + r;
    const int wrow = (n & 1) * Vv + (n >> 1);
    const int term = kb / 12;
    const int kk0 = (kb % 12) * 64;
    const float* src = W_mo + (size_t)wrow * 768 + kk0;
    char* tile = (char*)g_B2 + (size_t)(nt * NKB + kb) * KTILE_BYTES;

#pragma unroll
    for (int j = 0; j < 8; j++) {
        float4 x0 = *(const float4*)(src + j * 8);
        float4 x1 = *(const float4*)(src + j * 8 + 4);
        float xs[8] = {x0.x, x0.y, x0.z, x0.w, x1.x, x1.y, x1.z, x1.w};
        unsigned short o[8];
#pragma unroll
        for (int q = 0; q < 8; q++) {
            __nv_bfloat16 h = __float2bfloat16(xs[q]);
            if (term == 1) h = __float2bfloat16(xs[q] - __bfloat162float(h));
            o[q] = *(unsigned short*)&h;
        }
        uint32_t off = sw128((uint32_t)r * 128 + j * 16);
        *(uint4*)(tile + off) = *(uint4*)o;
    }
}

// conv_S: g_S (fp32 [4096][768]) -> g_A2. Terms: 0 = hi, 1 = hi, 2 = lo.
__global__ __launch_bounds__(128) void conv_S_kernel()
{
    const int kb = blockIdx.x, mt = blockIdx.y;
    const int r = threadIdx.x;                  // 0..127
    const int m = mt * 128 + r;
    const int term = kb / 12;
    const int kk0 = (kb % 12) * 64;
    const float* src = g_S + (size_t)m * 768 + kk0;
    char* tile = (char*)g_A2 + (size_t)(mt * NKB + kb) * KTILE_BYTES;

#pragma unroll
    for (int j = 0; j < 8; j++) {
        float4 x0 = *(const float4*)(src + j * 8);
        float4 x1 = *(const float4*)(src + j * 8 + 4);
        float xs[8] = {x0.x, x0.y, x0.z, x0.w, x1.x, x1.y, x1.z, x1.w};
        unsigned short o[8];
#pragma unroll
        for (int q = 0; q < 8; q++) {
            __nv_bfloat16 h = __float2bfloat16(xs[q]);
            if (term == 2) h = __float2bfloat16(xs[q] - __bfloat162float(h));
            o[q] = *(unsigned short*)&h;
        }
        uint32_t off = sw128((uint32_t)r * 128 + j * 16);
        *(uint4*)(tile + off) = *(uint4*)o;
    }
}

// ---------------------------------------------------------------------------
// mma.sync bf16 GEMM. CTA 128x128x64, 256 threads, 8 warps (4x2),
// warp tile 32x64, 3-stage cp.async. Fused pair-max + bias epilogue.
// ---------------------------------------------------------------------------
__global__ __launch_bounds__(256) void gemm_mma_kernel(
    float* __restrict__ out, const float* __restrict__ b_mo)
{
    extern __shared__ char dsm[];
    const uint32_t sbase = (smem_u32(dsm) + 127) & ~127u;

    const int tid = threadIdx.x;
    const int lane = tid & 31;
    const int wid = tid >> 5;
    const int wm = (wid & 3) * 32;      // warp m offset in tile
    const int wn = (wid >> 2) * 64;     // warp n offset in tile
    const int mt = blockIdx.x, nt = blockIdx.y;

    const char* Ab = (const char*)g_A2 + (size_t)mt * NKB * KTILE_BYTES;
    const char* Bbp = (const char*)g_B2 + (size_t)nt * NKB * KTILE_BYTES;

    auto load_stage = [&](int kb, int s) {
        uint32_t sa = sbase + s * STAGE_BYTES + tid * 16;
        const char* ga = Ab + (size_t)kb * KTILE_BYTES + tid * 16;
        const char* gb = Bbp + (size_t)kb * KTILE_BYTES + tid * 16;
#pragma unroll
        for (int i = 0; i < 4; i++) cp_async16(sa + i * 4096, ga + i * 4096);
        sa += 16384;
#pragma unroll
        for (int i = 0; i < 4; i++) cp_async16(sa + i * 4096, gb + i * 4096);
        cp_commit();
    };

    float acc[2][8][4];
#pragma unroll
    for (int i = 0; i < 2; i++)
#pragma unroll
        for (int j = 0; j < 8; j++)
#pragma unroll
            for (int q = 0; q < 4; q++) acc[i][j][q] = 0.f;

    load_stage(0, 0);
    load_stage(1, 1);

    // precomputed ldmatrix intra-tile offsets
    const uint32_t a_row = wm + (lane & 15);
    const uint32_t a_kb  = (lane >> 4) * 16;
    const uint32_t b_row = wn + (lane & 7) + ((lane >> 4) << 3);
    const uint32_t b_kb  = ((lane >> 3) & 1) * 16;

    for (int kb = 0; kb < NKB; kb++) {
        const int s = kb % NSTAGE;
        if (kb >= NKB - 1) asm volatile("cp.async.wait_group 0;" ::: "memory");
        else               asm volatile("cp.async.wait_group 1;" ::: "memory");
        __syncthreads();

        const uint32_t abase = sbase + s * STAGE_BYTES;
        const uint32_t bbase = abase + 16384;

#pragma unroll
        for (int ks = 0; ks < 4; ks++) {
            uint32_t afr[2][4];
#pragma unroll
            for (int i = 0; i < 2; i++) {
                uint32_t ad = abase + sw128((a_row + i * 16) * 128 + ks * 32 + a_kb);
                ldsm4(afr[i], ad);
            }
            uint32_t bfr[4][4];
#pragma unroll
            for (int j = 0; j < 4; j++) {
                uint32_t bd = bbase + sw128((b_row + j * 16) * 128 + ks * 32 + b_kb);
                ldsm4(bfr[j], bd);
            }
#pragma unroll
            for (int i = 0; i < 2; i++)
#pragma unroll
                for (int j = 0; j < 8; j++) {
                    uint32_t b0 = bfr[j >> 1][(j & 1) * 2];
                    uint32_t b1 = bfr[j >> 1][(j & 1) * 2 + 1];
                    mma16816(acc[i][j], afr[i], b0, b1);
                }
        }

        const int nxt = kb + 2;
        if (nxt < NKB) load_stage(nxt, nxt % NSTAGE);
    }

    // Epilogue: d0,d1 -> row lane/4, cols 2c,2c+1 ; d2,d3 -> row+8.
    // Global col pair (2p, 2p+1) maps to W_mo rows (p, V+p):
    // out[b][t][p] = max(even + b_mo[p], odd + b_mo[V+p]).
#pragma unroll
    for (int i = 0; i < 2; i++) {
        int mrow0 = mt * 128 + wm + i * 16 + (lane >> 2);
        int mrow1 = mrow0 + 8;
        int t0 = mrow0 >> 6, bb0 = mrow0 & 63;
        int t1 = mrow1 >> 6, bb1 = mrow1 & 63;
        float* orow0 = out + (size_t)bb0 * (TYy * Vv) + (size_t)t0 * Vv;
        float* orow1 = out + (size_t)bb1 * (TYy * Vv) + (size_t)t1 * Vv;
#pragma unroll
        for (int j = 0; j < 8; j++) {
            int ncol = nt * 128 + wn + j * 8 + (lane & 3) * 2;
            int p = ncol >> 1;
            float be = b_mo[p], bo = b_mo[Vv + p];
            orow0[p] = fmaxf(acc[i][j][0] + be, acc[i][j][1] + bo);
            orow1[p] = fmaxf(acc[i][j][2] + be, acc[i][j][3] + bo);
        }
    }
}

// ---------------------------------------------------------------------------
extern "C" void kernel_launch(void* const* d_in, const int* in_sizes, int n_in,
                              void* d_out, int out_size)
{
    const int*   y    = (const int*)d_in[0];
    const float* h_j  = (const float*)d_in[1];
    const float* emb  = (const float*)d_in[2];
    const float* W_ih = (const float*)d_in[3];
    const float* W_hh = (const float*)d_in[4];
    const float* b_ih = (const float*)d_in[5];
    const float* b_hh = (const float*)d_in[6];
    const float* W_a  = (const float*)d_in[7];
    const float* v_a  = (const float*)d_in[8];
    const float* W_mo = (const float*)d_in[9];
    const float* b_mo = (const float*)d_in[10];
    float* out = (float*)d_out;

    void* hjp_v; cudaGetSymbolAddress(&hjp_v, g_hjproj);
    float* hjp = (float*)hjp_v;

    const int smem_bytes = NSTAGE * STAGE_BYTES + 128;
    cudaFuncSetAttribute(gemm_mma_kernel,
                         cudaFuncAttributeMaxDynamicSharedMemorySize, smem_bytes);

    // W_mo -> bf16 split tiles (independent of recurrence)
    conv_W_kernel<<<dim3(NKB, 500), 128>>>(W_mo);

    // hj_proj: (B*TX, 512) @ W_a[:,256:768]^T
    sgemm_nt<<<dim3((Bb * TXx) / 128, Hh / 128), 256>>>(
        Bb * TXx, Hh, 2 * Hh, h_j, 2 * Hh, W_a + Hh, 3 * Hh, hjp);

    emb_gemm_kernel<<<(TYy * Bb) / 16, 256>>>(y, emb, W_ih, b_ih);

    for (int t = 0; t < TYy; t++)
        step_kernel<<<Bb, 256>>>(t, h_j, W_ih, W_hh, b_hh, W_a, v_a);

    // S -> bf16 split tiles, then HMMA GEMM with fused max epilogue
    conv_S_kernel<<<dim3(NKB, 32), 128>>>();
    gemm_mma_kernel<<<dim3(32, 500), 256, smem_bytes>>>(out, b_mo);
}

// round 8
// speedup vs baseline: 2.7313x; 1.7482x over previous
#include <cuda_runtime.h>
#include <cuda_bf16.h>
#include <math.h>
#include <stdint.h>

#define Vv 32000
#define Ee 128
#define Hh 256
#define Bb 64
#define TYy 64
#define TXx 128

#define NKB 36             // K-blocks of 64 bf16 (K_eff = 3*768 = 2304)
#define KTILE_BYTES 16384  // 128 rows x 64 bf16 (swizzled)
#define STAGE_BYTES 32768  // A tile + B tile
#define NSTAGE 3

// Scratch (device globals — no allocation allowed)
__device__ float g_hjproj[Bb * TXx * Hh];
__device__ float g_gi_emb[TYy * Bb * 768];
__device__ float g_S[TYy * Bb * 768];   // [t][b]{ s_i(256), c_new(512) }
// bf16-split tiled operands for the big GEMM (pre-swizzled 128x64 tiles)
__device__ __align__(128) unsigned short g_A2[32 * NKB * 8192];    // 32 m-tiles
__device__ __align__(128) unsigned short g_B2[500 * NKB * 8192];   // 500 n-tiles

__device__ __forceinline__ float sigmoidf_(float x) { return 1.f / (1.f + expf(-x)); }
__device__ __forceinline__ float tanh_fast(float x) {
    float y; asm("tanh.approx.f32 %0, %1;" : "=f"(y) : "f"(x)); return y;
}
__device__ __forceinline__ uint32_t smem_u32(const void* p) {
    uint32_t a;
    asm("{ .reg .u64 t; cvta.to.shared.u64 t, %1; cvt.u32.u64 %0, t; }" : "=r"(a) : "l"(p));
    return a;
}
__device__ __forceinline__ uint32_t sw128(uint32_t off) { return off ^ ((off >> 3) & 0x70); }

__device__ __forceinline__ void cp_async16(uint32_t saddr, const void* g) {
    asm volatile("cp.async.cg.shared.global [%0], [%1], 16;" :: "r"(saddr), "l"(g));
}
__device__ __forceinline__ void cp_commit() { asm volatile("cp.async.commit_group;"); }

__device__ __forceinline__ void ldsm4(uint32_t* r, uint32_t addr) {
    asm volatile("ldmatrix.sync.aligned.m8n8.x4.shared.b16 {%0,%1,%2,%3}, [%4];"
                 : "=r"(r[0]), "=r"(r[1]), "=r"(r[2]), "=r"(r[3]) : "r"(addr));
}
__device__ __forceinline__ void mma16816(float* d, const uint32_t* a, uint32_t b0, uint32_t b1) {
    asm volatile("mma.sync.aligned.m16n8k16.row.col.f32.bf16.bf16.f32 "
                 "{%0,%1,%2,%3}, {%4,%5,%6,%7}, {%8,%9}, {%0,%1,%2,%3};"
                 : "+f"(d[0]), "+f"(d[1]), "+f"(d[2]), "+f"(d[3])
                 : "r"(a[0]), "r"(a[1]), "r"(a[2]), "r"(a[3]), "r"(b0), "r"(b1));
}

// ---------------------------------------------------------------------------
// K1: gi_emb = b_ih + emb_eff[y] @ W_ih[:, :128].T
// ---------------------------------------------------------------------------
__global__ __launch_bounds__(256) void emb_gemm_kernel(
    const int* __restrict__ y, const float* __restrict__ emb,
    const float* __restrict__ W_ih, const float* __restrict__ b_ih)
{
    __shared__ float Xs[16][128];
    const int tid = threadIdx.x;
    const int m_base = blockIdx.x * 16;

    for (int idx = tid; idx < 16 * 128; idx += 256) {
        int i = idx >> 7, k = idx & 127;
        int m = m_base + i;
        int tt = m >> 6, bb = m & 63;
        int yv = y[bb * TYy + tt];
        Xs[i][k] = (yv == 0) ? 0.f : emb[(size_t)yv * Ee + k];
    }
    __syncthreads();

    float acc0[16], acc1[16], acc2[16];
#pragma unroll
    for (int i = 0; i < 16; i++) { acc0[i] = 0.f; acc1[i] = 0.f; acc2[i] = 0.f; }

    const float* w0 = W_ih + (size_t)tid * 640;
    const float* w1 = W_ih + (size_t)(tid + 256) * 640;
    const float* w2 = W_ih + (size_t)(tid + 512) * 640;

    for (int k = 0; k < 128; k++) {
        float a = w0[k], b = w1[k], c = w2[k];
#pragma unroll
        for (int i = 0; i < 16; i++) {
            float x = Xs[i][k];
            acc0[i] = fmaf(x, a, acc0[i]);
            acc1[i] = fmaf(x, b, acc1[i]);
            acc2[i] = fmaf(x, c, acc2[i]);
        }
    }
    float bi0 = b_ih[tid], bi1 = b_ih[tid + 256], bi2 = b_ih[tid + 512];
#pragma unroll
    for (int i = 0; i < 16; i++) {
        size_t base = (size_t)(m_base + i) * 768;
        g_gi_emb[base + tid]       = acc0[i] + bi0;
        g_gi_emb[base + tid + 256] = acc1[i] + bi1;
        g_gi_emb[base + tid + 512] = acc2[i] + bi2;
    }
}

// ---------------------------------------------------------------------------
// K2a: gates for ALL batches as a tiled GEMM. 64 blocks; block jb owns hidden
// units u = jb*4 .. jb*4+3 (matrix rows {u, 256+u, 512+u}) for all 64 batches.
// Weights are read exactly ONCE per step chip-wide (vs 64x before).
// X = [c_i (512) | h_i (256)] per batch; K = 768 in 12 chunks of 64.
// n-gate keeps c-part (a_in) and h-part (a_hn) separate for r*hn.
// ---------------------------------------------------------------------------
__global__ __launch_bounds__(256) void gates_kernel(
    int t, const float* __restrict__ W_ih, const float* __restrict__ W_hh,
    const float* __restrict__ b_hh)
{
    const int jb = blockIdx.x;          // 0..63
    const int tid = threadIdx.x;
    const int b = tid & 63;             // batch this thread computes
    const int rg = tid >> 6;            // unit-in-block 0..3

    __shared__ float Xs[64][64];        // [kk][b]
    __shared__ float4 Ws[12][16];       // [row][kk4], rows: 0-3 r, 4-7 z, 8-11 n

    const float* Sprev = g_S + (size_t)(t - 1) * Bb * 768;  // guarded by t>0
    const int u0 = jb * 4;

    float a_r = 0.f, a_z = 0.f, a_in = 0.f, a_hn = 0.f;

    const int lb = tid >> 2;            // load: batch row
    const int lq = tid & 3;             // load: kk quarter

    for (int kc = 0; kc < 12; kc++) {
        const int k0 = kc * 64;
        const bool cpart = (k0 < 512);

        if (t == 0) {
#pragma unroll
            for (int i = 0; i < 4; i++) {
                int kk = lq * 16 + i * 4;
                Xs[kk + 0][lb] = 0.f; Xs[kk + 1][lb] = 0.f;
                Xs[kk + 2][lb] = 0.f; Xs[kk + 3][lb] = 0.f;
            }
        } else {
            const float* src = Sprev + (size_t)lb * 768 + (cpart ? 256 + k0 : k0 - 512);
#pragma unroll
            for (int i = 0; i < 4; i++) {
                int kk = lq * 16 + i * 4;
                float4 v = *(const float4*)(src + kk);
                Xs[kk + 0][lb] = v.x; Xs[kk + 1][lb] = v.y;
                Xs[kk + 2][lb] = v.z; Xs[kk + 3][lb] = v.w;
            }
        }
        if (tid < 192) {
            int r = tid >> 4, q = tid & 15;
            int g = r >> 2, ru = r & 3;
            int row = g * 256 + u0 + ru;
            const float* wsrc = cpart ? (W_ih + (size_t)row * 640 + 128 + k0)
                                      : (W_hh + (size_t)row * 256 + (k0 - 512));
            Ws[r][q] = *(const float4*)(wsrc + q * 4);
        }
        __syncthreads();

        float ax = 0.f;
#pragma unroll
        for (int kk4 = 0; kk4 < 16; kk4++) {
            float4 wr = Ws[rg][kk4];
            float4 wz = Ws[4 + rg][kk4];
            float4 wn = Ws[8 + rg][kk4];
            float x0 = Xs[kk4 * 4 + 0][b];
            float x1 = Xs[kk4 * 4 + 1][b];
            float x2 = Xs[kk4 * 4 + 2][b];
            float x3 = Xs[kk4 * 4 + 3][b];
            a_r = fmaf(x0, wr.x, fmaf(x1, wr.y, fmaf(x2, wr.z, fmaf(x3, wr.w, a_r))));
            a_z = fmaf(x0, wz.x, fmaf(x1, wz.y, fmaf(x2, wz.z, fmaf(x3, wz.w, a_z))));
            ax  = fmaf(x0, wn.x, fmaf(x1, wn.y, fmaf(x2, wn.z, fmaf(x3, wn.w, ax))));
        }
        if (cpart) a_in += ax; else a_hn += ax;
        __syncthreads();
    }

    const int uu = u0 + rg;
    const size_t gib = ((size_t)t * Bb + b) * 768;
    float gr = a_r + g_gi_emb[gib + uu] + b_hh[uu];
    float gz = a_z + g_gi_emb[gib + 256 + uu] + b_hh[256 + uu];
    float hn = a_hn + b_hh[512 + uu];
    float gn = a_in + g_gi_emb[gib + 512 + uu];
    float r = sigmoidf_(gr);
    float z = sigmoidf_(gz);
    float n = tanhf(gn + r * hn);
    float hprev = (t == 0) ? 0.f : Sprev[(size_t)b * 768 + uu];
    float s = (1.f - z) * n + z * hprev;
    g_S[gib + uu] = s;
}

// ---------------------------------------------------------------------------
// K2b: attention + context per batch. 64 blocks, 256 threads.
// ---------------------------------------------------------------------------
__global__ __launch_bounds__(256) void attn_kernel(
    int t, const float* __restrict__ h_j, const float* __restrict__ W_a,
    const float* __restrict__ v_a)
{
    const int b = blockIdx.x;
    const int tid = threadIdx.x;

    __shared__ float si_s[256];
    __shared__ float sp_s[256];
    __shared__ float e_s[128];
    __shared__ float red_s[128];
    __shared__ float va_s[256];

    const size_t gbase = ((size_t)t * Bb + b) * 768;
    si_s[tid] = g_S[gbase + tid];
    va_s[tid] = v_a[tid];
    __syncthreads();

    // s_proj[h] = sum_k s_i[k] * W_a[h][k] (k < 256)
    {
        float sp = 0.f;
        const float4* wa = (const float4*)(W_a + (size_t)tid * 768);
        const float4* sip = (const float4*)si_s;
#pragma unroll 8
        for (int k4 = 0; k4 < 64; k4++) {
            float4 sv = sip[k4];
            float4 w = wa[k4];
            sp += sv.x * w.x + sv.y * w.y + sv.z * w.z + sv.w * w.w;
        }
        sp_s[tid] = sp;
    }
    __syncthreads();

    // energy over TX=128 (first 128 threads), vectorized
    if (tid < 128) {
        const float4* hp = (const float4*)(g_hjproj + ((size_t)b * TXx + tid) * Hh);
        const float4* spv = (const float4*)sp_s;
        const float4* vav = (const float4*)va_s;
        float e = 0.f;
#pragma unroll 4
        for (int h4 = 0; h4 < 64; h4++) {
            float4 h = hp[h4];
            float4 s = spv[h4];
            float4 v = vav[h4];
            e += tanh_fast(s.x + h.x) * v.x;
            e += tanh_fast(s.y + h.y) * v.y;
            e += tanh_fast(s.z + h.z) * v.z;
            e += tanh_fast(s.w + h.w) * v.w;
        }
        e_s[tid] = e;
        red_s[tid] = e;
    }
    __syncthreads();
    for (int st = 64; st > 0; st >>= 1) {
        if (tid < st) red_s[tid] = fmaxf(red_s[tid], red_s[tid + st]);
        __syncthreads();
    }
    float mx = red_s[0];
    __syncthreads();
    if (tid < 128) {
        float ex = expf(e_s[tid] - mx);
        e_s[tid] = ex;
        red_s[tid] = ex;
    }
    __syncthreads();
    for (int st = 64; st > 0; st >>= 1) {
        if (tid < st) red_s[tid] += red_s[tid + st];
        __syncthreads();
    }
    float inv = 1.f / red_s[0];
    __syncthreads();
    if (tid < 128) e_s[tid] *= inv;
    __syncthreads();

    // c_new[k] = sum_t' alpha[t'] * h_j[b][t'][k]
    float c0 = 0.f, c1 = 0.f;
    const float* hjb = h_j + (size_t)b * TXx * 512;
#pragma unroll 8
    for (int tp = 0; tp < 128; tp++) {
        float al = e_s[tp];
        c0 = fmaf(al, hjb[(size_t)tp * 512 + tid], c0);
        c1 = fmaf(al, hjb[(size_t)tp * 512 + 256 + tid], c1);
    }
    g_S[gbase + 256 + tid] = c0;
    g_S[gbase + 512 + tid] = c1;
}

// ---------------------------------------------------------------------------
// fp32 SIMT SGEMM (only for hj_proj)
// ---------------------------------------------------------------------------
__global__ __launch_bounds__(256) void sgemm_nt(
    int M, int N, int K,
    const float* __restrict__ A, int lda,
    const float* __restrict__ B, int ldb,
    float* __restrict__ C)
{
    constexpr int BMs = 128, BNs = 128, BKs = 16;
    __shared__ float As[2][BKs][BMs];
    __shared__ float Bs[2][BKs][BNs];

    const int tid = threadIdx.x;
    const int m0 = blockIdx.x * BMs;
    const int n0 = blockIdx.y * BNs;
    const int tx = tid & 15;
    const int ty = tid >> 4;
    const int lRow = tid >> 1;
    const int lK = (tid & 1) * 8;

    const float* Aptr = A + (size_t)(m0 + lRow) * lda + lK;
    const float* Bptr = B + (size_t)(n0 + lRow) * ldb + lK;

    float acc[8][8];
#pragma unroll
    for (int i = 0; i < 8; i++)
#pragma unroll
        for (int j = 0; j < 8; j++) acc[i][j] = 0.f;

    const int nk = K / BKs;
    float4 ar0, ar1, br0, br1;
    ar0 = *(const float4*)(Aptr);
    ar1 = *(const float4*)(Aptr + 4);
    br0 = *(const float4*)(Bptr);
    br1 = *(const float4*)(Bptr + 4);
#pragma unroll
    for (int q = 0; q < 4; q++) {
        As[0][lK + q][lRow] = ((const float*)&ar0)[q];
        As[0][lK + 4 + q][lRow] = ((const float*)&ar1)[q];
        Bs[0][lK + q][lRow] = ((const float*)&br0)[q];
        Bs[0][lK + 4 + q][lRow] = ((const float*)&br1)[q];
    }
    __syncthreads();

    for (int kt = 0; kt < nk; kt++) {
        const int cur = kt & 1;
        const bool has_next = (kt + 1 < nk);
        if (has_next) {
            const float* Ap = Aptr + (kt + 1) * BKs;
            const float* Bp = Bptr + (kt + 1) * BKs;
            ar0 = *(const float4*)(Ap);
            ar1 = *(const float4*)(Ap + 4);
            br0 = *(const float4*)(Bp);
            br1 = *(const float4*)(Bp + 4);
        }
#pragma unroll
        for (int kk = 0; kk < BKs; kk++) {
            float4 a0 = *(const float4*)&As[cur][kk][ty * 8];
            float4 a1 = *(const float4*)&As[cur][kk][ty * 8 + 4];
            float4 b0 = *(const float4*)&Bs[cur][kk][tx * 8];
            float4 b1 = *(const float4*)&Bs[cur][kk][tx * 8 + 4];
            float av[8] = {a0.x, a0.y, a0.z, a0.w, a1.x, a1.y, a1.z, a1.w};
            float bv[8] = {b0.x, b0.y, b0.z, b0.w, b1.x, b1.y, b1.z, b1.w};
#pragma unroll
            for (int i = 0; i < 8; i++)
#pragma unroll
                for (int j = 0; j < 8; j++)
                    acc[i][j] = fmaf(av[i], bv[j], acc[i][j]);
        }
        if (has_next) {
            const int nxt = cur ^ 1;
#pragma unroll
            for (int q = 0; q < 4; q++) {
                As[nxt][lK + q][lRow] = ((const float*)&ar0)[q];
                As[nxt][lK + 4 + q][lRow] = ((const float*)&ar1)[q];
                Bs[nxt][lK + q][lRow] = ((const float*)&br0)[q];
                Bs[nxt][lK + 4 + q][lRow] = ((const float*)&br1)[q];
            }
            __syncthreads();
        }
    }
#pragma unroll
    for (int i = 0; i < 8; i++) {
        float* crow = C + (size_t)(m0 + ty * 8 + i) * N + n0 + tx * 8;
        float4 v0 = {acc[i][0], acc[i][1], acc[i][2], acc[i][3]};
        float4 v1 = {acc[i][4], acc[i][5], acc[i][6], acc[i][7]};
        *(float4*)(crow) = v0;
        *(float4*)(crow + 4) = v1;
    }
}

// ---------------------------------------------------------------------------
// conv_W: W_mo (fp32, interleave-reordered rows) -> g_B2 bf16 split tiles.
// Terms along K: 0 = hi, 1 = lo, 2 = hi.
// ---------------------------------------------------------------------------
__global__ __launch_bounds__(128) void conv_W_kernel(const float* __restrict__ W_mo)
{
    const int kb = blockIdx.x, nt = blockIdx.y;
    const int r = threadIdx.x;                  // 0..127
    const int n = nt * 128 + r;
    const int wrow = (n & 1) * Vv + (n >> 1);
    const int term = kb / 12;
    const int kk0 = (kb % 12) * 64;
    const float* src = W_mo + (size_t)wrow * 768 + kk0;
    char* tile = (char*)g_B2 + (size_t)(nt * NKB + kb) * KTILE_BYTES;

#pragma unroll
    for (int j = 0; j < 8; j++) {
        float4 x0 = *(const float4*)(src + j * 8);
        float4 x1 = *(const float4*)(src + j * 8 + 4);
        float xs[8] = {x0.x, x0.y, x0.z, x0.w, x1.x, x1.y, x1.z, x1.w};
        unsigned short o[8];
#pragma unroll
        for (int q = 0; q < 8; q++) {
            __nv_bfloat16 h = __float2bfloat16(xs[q]);
            if (term == 1) h = __float2bfloat16(xs[q] - __bfloat162float(h));
            o[q] = *(unsigned short*)&h;
        }
        uint32_t off = sw128((uint32_t)r * 128 + j * 16);
        *(uint4*)(tile + off) = *(uint4*)o;
    }
}

// conv_S: g_S (fp32 [4096][768]) -> g_A2. Terms: 0 = hi, 1 = hi, 2 = lo.
__global__ __launch_bounds__(128) void conv_S_kernel()
{
    const int kb = blockIdx.x, mt = blockIdx.y;
    const int r = threadIdx.x;                  // 0..127
    const int m = mt * 128 + r;
    const int term = kb / 12;
    const int kk0 = (kb % 12) * 64;
    const float* src = g_S + (size_t)m * 768 + kk0;
    char* tile = (char*)g_A2 + (size_t)(mt * NKB + kb) * KTILE_BYTES;

#pragma unroll
    for (int j = 0; j < 8; j++) {
        float4 x0 = *(const float4*)(src + j * 8);
        float4 x1 = *(const float4*)(src + j * 8 + 4);
        float xs[8] = {x0.x, x0.y, x0.z, x0.w, x1.x, x1.y, x1.z, x1.w};
        unsigned short o[8];
#pragma unroll
        for (int q = 0; q < 8; q++) {
            __nv_bfloat16 h = __float2bfloat16(xs[q]);
            if (term == 2) h = __float2bfloat16(xs[q] - __bfloat162float(h));
            o[q] = *(unsigned short*)&h;
        }
        uint32_t off = sw128((uint32_t)r * 128 + j * 16);
        *(uint4*)(tile + off) = *(uint4*)o;
    }
}

// ---------------------------------------------------------------------------
// mma.sync bf16 GEMM. CTA 128x128x64, 256 threads, 8 warps (4x2),
// warp tile 32x64, 3-stage cp.async. Fused pair-max + bias epilogue.
// ---------------------------------------------------------------------------
__global__ __launch_bounds__(256) void gemm_mma_kernel(
    float* __restrict__ out, const float* __restrict__ b_mo)
{
    extern __shared__ char dsm[];
    const uint32_t sbase = (smem_u32(dsm) + 127) & ~127u;

    const int tid = threadIdx.x;
    const int lane = tid & 31;
    const int wid = tid >> 5;
    const int wm = (wid & 3) * 32;      // warp m offset in tile
    const int wn = (wid >> 2) * 64;     // warp n offset in tile
    const int mt = blockIdx.x, nt = blockIdx.y;

    const char* Ab = (const char*)g_A2 + (size_t)mt * NKB * KTILE_BYTES;
    const char* Bbp = (const char*)g_B2 + (size_t)nt * NKB * KTILE_BYTES;

    auto load_stage = [&](int kb, int s) {
        uint32_t sa = sbase + s * STAGE_BYTES + tid * 16;
        const char* ga = Ab + (size_t)kb * KTILE_BYTES + tid * 16;
        const char* gb = Bbp + (size_t)kb * KTILE_BYTES + tid * 16;
#pragma unroll
        for (int i = 0; i < 4; i++) cp_async16(sa + i * 4096, ga + i * 4096);
        sa += 16384;
#pragma unroll
        for (int i = 0; i < 4; i++) cp_async16(sa + i * 4096, gb + i * 4096);
        cp_commit();
    };

    float acc[2][8][4];
#pragma unroll
    for (int i = 0; i < 2; i++)
#pragma unroll
        for (int j = 0; j < 8; j++)
#pragma unroll
            for (int q = 0; q < 4; q++) acc[i][j][q] = 0.f;

    load_stage(0, 0);
    load_stage(1, 1);

    const uint32_t a_row = wm + (lane & 15);
    const uint32_t a_kb  = (lane >> 4) * 16;
    const uint32_t b_row = wn + (lane & 7) + ((lane >> 4) << 3);
    const uint32_t b_kb  = ((lane >> 3) & 1) * 16;

    for (int kb = 0; kb < NKB; kb++) {
        const int s = kb % NSTAGE;
        if (kb >= NKB - 1) asm volatile("cp.async.wait_group 0;" ::: "memory");
        else               asm volatile("cp.async.wait_group 1;" ::: "memory");
        __syncthreads();

        const uint32_t abase = sbase + s * STAGE_BYTES;
        const uint32_t bbase = abase + 16384;

#pragma unroll
        for (int ks = 0; ks < 4; ks++) {
            uint32_t afr[2][4];
#pragma unroll
            for (int i = 0; i < 2; i++) {
                uint32_t ad = abase + sw128((a_row + i * 16) * 128 + ks * 32 + a_kb);
                ldsm4(afr[i], ad);
            }
            uint32_t bfr[4][4];
#pragma unroll
            for (int j = 0; j < 4; j++) {
                uint32_t bd = bbase + sw128((b_row + j * 16) * 128 + ks * 32 + b_kb);
                ldsm4(bfr[j], bd);
            }
#pragma unroll
            for (int i = 0; i < 2; i++)
#pragma unroll
                for (int j = 0; j < 8; j++) {
                    uint32_t b0 = bfr[j >> 1][(j & 1) * 2];
                    uint32_t b1 = bfr[j >> 1][(j & 1) * 2 + 1];
                    mma16816(acc[i][j], afr[i], b0, b1);
                }
        }

        const int nxt = kb + 2;
        if (nxt < NKB) load_stage(nxt, nxt % NSTAGE);
    }

#pragma unroll
    for (int i = 0; i < 2; i++) {
        int mrow0 = mt * 128 + wm + i * 16 + (lane >> 2);
        int mrow1 = mrow0 + 8;
        int t0 = mrow0 >> 6, bb0 = mrow0 & 63;
        int t1 = mrow1 >> 6, bb1 = mrow1 & 63;
        float* orow0 = out + (size_t)bb0 * (TYy * Vv) + (size_t)t0 * Vv;
        float* orow1 = out + (size_t)bb1 * (TYy * Vv) + (size_t)t1 * Vv;
#pragma unroll
        for (int j = 0; j < 8; j++) {
            int ncol = nt * 128 + wn + j * 8 + (lane & 3) * 2;
            int p = ncol >> 1;
            float be = b_mo[p], bo = b_mo[Vv + p];
            orow0[p] = fmaxf(acc[i][j][0] + be, acc[i][j][1] + bo);
            orow1[p] = fmaxf(acc[i][j][2] + be, acc[i][j][3] + bo);
        }
    }
}

// ---------------------------------------------------------------------------
extern "C" void kernel_launch(void* const* d_in, const int* in_sizes, int n_in,
                              void* d_out, int out_size)
{
    const int*   y    = (const int*)d_in[0];
    const float* h_j  = (const float*)d_in[1];
    const float* emb  = (const float*)d_in[2];
    const float* W_ih = (const float*)d_in[3];
    const float* W_hh = (const float*)d_in[4];
    const float* b_ih = (const float*)d_in[5];
    const float* b_hh = (const float*)d_in[6];
    const float* W_a  = (const float*)d_in[7];
    const float* v_a  = (const float*)d_in[8];
    const float* W_mo = (const float*)d_in[9];
    const float* b_mo = (const float*)d_in[10];
    float* out = (float*)d_out;

    void* hjp_v; cudaGetSymbolAddress(&hjp_v, g_hjproj);
    float* hjp = (float*)hjp_v;

    const int smem_bytes = NSTAGE * STAGE_BYTES + 128;
    cudaFuncSetAttribute(gemm_mma_kernel,
                         cudaFuncAttributeMaxDynamicSharedMemorySize, smem_bytes);

    // W_mo -> bf16 split tiles (independent of recurrence)
    conv_W_kernel<<<dim3(NKB, 500), 128>>>(W_mo);

    // hj_proj: (B*TX, 512) @ W_a[:,256:768]^T
    sgemm_nt<<<dim3((Bb * TXx) / 128, Hh / 128), 256>>>(
        Bb * TXx, Hh, 2 * Hh, h_j, 2 * Hh, W_a + Hh, 3 * Hh, hjp);

    emb_gemm_kernel<<<(TYy * Bb) / 16, 256>>>(y, emb, W_ih, b_ih);

    // sequential recurrence: gates (batched GEMM) then attention per step
    for (int t = 0; t < TYy; t++) {
        gates_kernel<<<64, 256>>>(t, W_ih, W_hh, b_hh);
        attn_kernel<<<Bb, 256>>>(t, h_j, W_a, v_a);
    }

    // S -> bf16 split tiles, then HMMA GEMM with fused max epilogue
    conv_S_kernel<<<dim3(NKB, 32), 128>>>();
    gemm_mma_kernel<<<dim3(32, 500), 256, smem_bytes>>>(out, b_mo);
}

// round 9
// speedup vs baseline: 2.9437x; 1.0778x over previous
#include <cuda_runtime.h>
#include <cuda_bf16.h>
#include <math.h>
#include <stdint.h>

#define Vv 32000
#define Ee 128
#define Hh 256
#define Bb 64
#define TYy 64
#define TXx 128

#define NKB 36             // K-blocks of 64 bf16 (K_eff = 3*768 = 2304)
#define KTILE_BYTES 16384  // 128 rows x 64 bf16 (swizzled)
#define STAGE_BYTES 32768  // A tile + B tile
#define NSTAGE 3
#define RB 128             // recurrence blocks

// Scratch (device globals — no allocation allowed)
__device__ float g_hjproj[Bb * TXx * Hh];
__device__ float g_gi_emb[TYy * Bb * 768];
__device__ float g_S[TYy * Bb * 768];   // [t][b]{ s_i(256), c_new(512) }
__device__ unsigned g_bar_ctr;
// bf16-split tiled operands for the big GEMM (pre-swizzled 128x64 tiles)
__device__ __align__(128) unsigned short g_A2[32 * NKB * 8192];    // 32 m-tiles
__device__ __align__(128) unsigned short g_B2[500 * NKB * 8192];   // 500 n-tiles

__device__ __forceinline__ float tanh_fast(float x) {
    float y; asm("tanh.approx.f32 %0, %1;" : "=f"(y) : "f"(x)); return y;
}
__device__ __forceinline__ uint32_t smem_u32(const void* p) {
    uint32_t a;
    asm("{ .reg .u64 t; cvta.to.shared.u64 t, %1; cvt.u32.u64 %0, t; }" : "=r"(a) : "l"(p));
    return a;
}
__device__ __forceinline__ uint32_t sw128(uint32_t off) { return off ^ ((off >> 3) & 0x70); }

__device__ __forceinline__ void cp_async16(uint32_t saddr, const void* g) {
    asm volatile("cp.async.cg.shared.global [%0], [%1], 16;" :: "r"(saddr), "l"(g));
}
__device__ __forceinline__ void cp_commit() { asm volatile("cp.async.commit_group;"); }

__device__ __forceinline__ void ldsm4(uint32_t* r, uint32_t addr) {
    asm volatile("ldmatrix.sync.aligned.m8n8.x4.shared.b16 {%0,%1,%2,%3}, [%4];"
                 : "=r"(r[0]), "=r"(r[1]), "=r"(r[2]), "=r"(r[3]) : "r"(addr));
}
__device__ __forceinline__ void mma16816(float* d, const uint32_t* a, uint32_t b0, uint32_t b1) {
    asm volatile("mma.sync.aligned.m16n8k16.row.col.f32.bf16.bf16.f32 "
                 "{%0,%1,%2,%3}, {%4,%5,%6,%7}, {%8,%9}, {%0,%1,%2,%3};"
                 : "+f"(d[0]), "+f"(d[1]), "+f"(d[2]), "+f"(d[3])
                 : "r"(a[0]), "r"(a[1]), "r"(a[2]), "r"(a[3]), "r"(b0), "r"(b1));
}

__global__ void reset_bar_kernel() { g_bar_ctr = 0; }

__device__ __forceinline__ void grid_bar(unsigned target) {
    __syncthreads();
    if (threadIdx.x == 0) {
        __threadfence();
        atomicAdd(&g_bar_ctr, 1u);
        while (*(volatile unsigned*)&g_bar_ctr < target) __nanosleep(32);
        __threadfence();
    }
    __syncthreads();
}

// ---------------------------------------------------------------------------
// K1: gi_emb = b_ih + emb_eff[y] @ W_ih[:, :128].T
// ---------------------------------------------------------------------------
__global__ __launch_bounds__(256) void emb_gemm_kernel(
    const int* __restrict__ y, const float* __restrict__ emb,
    const float* __restrict__ W_ih, const float* __restrict__ b_ih)
{
    __shared__ float Xs[16][128];
    const int tid = threadIdx.x;
    const int m_base = blockIdx.x * 16;

    for (int idx = tid; idx < 16 * 128; idx += 256) {
        int i = idx >> 7, k = idx & 127;
        int m = m_base + i;
        int tt = m >> 6, bb = m & 63;
        int yv = y[bb * TYy + tt];
        Xs[i][k] = (yv == 0) ? 0.f : emb[(size_t)yv * Ee + k];
    }
    __syncthreads();

    float acc0[16], acc1[16], acc2[16];
#pragma unroll
    for (int i = 0; i < 16; i++) { acc0[i] = 0.f; acc1[i] = 0.f; acc2[i] = 0.f; }

    const float* w0 = W_ih + (size_t)tid * 640;
    const float* w1 = W_ih + (size_t)(tid + 256) * 640;
    const float* w2 = W_ih + (size_t)(tid + 512) * 640;

    for (int k = 0; k < 128; k++) {
        float a = w0[k], b = w1[k], c = w2[k];
#pragma unroll
        for (int i = 0; i < 16; i++) {
            float x = Xs[i][k];
            acc0[i] = fmaf(x, a, acc0[i]);
            acc1[i] = fmaf(x, b, acc1[i]);
            acc2[i] = fmaf(x, c, acc2[i]);
        }
    }
    float bi0 = b_ih[tid], bi1 = b_ih[tid + 256], bi2 = b_ih[tid + 512];
#pragma unroll
    for (int i = 0; i < 16; i++) {
        size_t base = (size_t)(m_base + i) * 768;
        g_gi_emb[base + tid]       = acc0[i] + bi0;
        g_gi_emb[base + tid + 256] = acc1[i] + bi1;
        g_gi_emb[base + tid + 512] = acc2[i] + bi2;
    }
}

// ---------------------------------------------------------------------------
// Persistent recurrence kernel: 128 blocks x 256 threads, custom grid barrier.
// Gates: block owns 2 hidden units (6 gate rows) cached in smem; register-tiled
// GEMM (4 batches x 6 rows per thread, 16-way K split). Attn: blocks 0..63.
// Dyn smem layout (floats): Wk[768*8] @0, Xs[2*64*64] @6144 (also reduce
// scratch), attn arrays @14336 (si 256, sp 256, va 256, e 128, red 128).
// ---------------------------------------------------------------------------
__global__ __launch_bounds__(256, 1) void recur_kernel(
    const float* __restrict__ h_j, const float* __restrict__ W_ih,
    const float* __restrict__ W_hh, const float* __restrict__ b_hh,
    const float* __restrict__ W_a, const float* __restrict__ v_a)
{
    extern __shared__ float sm[];
    float* Wk   = sm;              // [768][8]
    float* Xs   = sm + 6144;       // [2][64][64]
    float* si_s = sm + 14336;
    float* sp_s = si_s + 256;
    float* va_s = sp_s + 256;
    float* e_s  = va_s + 256;
    float* red_s = e_s + 128;

    const int tid = threadIdx.x;
    const int blk = blockIdx.x;
    const int bg = tid & 15, ks = tid >> 4;
    const int wid = tid >> 5, lane = tid & 31;
    const int lb = tid & 63, lq = tid >> 6;     // staging roles

    // one-time: preload this block's 6 gate rows into Wk[k][r], r = g*2+i
    for (int r = 0; r < 6; r++) {
        int g = r >> 1, i = r & 1;
        int row = g * 256 + blk * 2 + i;
        const float* wih = W_ih + (size_t)row * 640 + 128;
        const float* whh = W_hh + (size_t)row * 256;
        for (int k = tid; k < 768; k += 256)
            Wk[k * 8 + r] = (k < 512) ? wih[k] : whh[k - 512];
    }
    for (int k = tid; k < 768; k += 256) { Wk[k * 8 + 6] = 0.f; Wk[k * 8 + 7] = 0.f; }
    va_s[tid] = v_a[tid];

    unsigned bar_target = 0;

    for (int t = 0; t < TYy; t++) {
        const float* Sprev = g_S + (size_t)(t - 1) * Bb * 768;

        float acc[4][6], anc[4][2];
#pragma unroll
        for (int a = 0; a < 4; a++) {
#pragma unroll
            for (int r = 0; r < 6; r++) acc[a][r] = 0.f;
            anc[a][0] = 0.f; anc[a][1] = 0.f;
        }

        if (t > 0) {
            const float* srow = Sprev + (size_t)lb * 768;
            // stage chunk 0 (c-part, src offset 256) transposed into buf 0
#pragma unroll
            for (int j = 0; j < 4; j++) {
                int kl = lq * 16 + j * 4;
                float4 v = *(const float4*)(srow + 256 + kl);
                float* dst = Xs + kl * 64 + lb;
                dst[0] = v.x; dst[64] = v.y; dst[128] = v.z; dst[192] = v.w;
            }
            for (int c = 0; c < 12; c++) {
                __syncthreads();
                float4 pf[4];
                if (c < 11) {
                    int cn = c + 1;
                    int base = (cn < 8) ? (256 + cn * 64) : (cn * 64 - 512);
#pragma unroll
                    for (int j = 0; j < 4; j++)
                        pf[j] = *(const float4*)(srow + base + lq * 16 + j * 4);
                }
                const float* XB = Xs + (c & 1) * 4096;
#pragma unroll
                for (int kq = 0; kq < 4; kq++) {
                    int kl = ks * 4 + kq;
                    int kg = c * 64 + kl;
                    float4 xv = *(const float4*)(XB + kl * 64 + bg * 4);
                    float4 w0 = *(const float4*)(Wk + kg * 8);
                    float4 w1 = *(const float4*)(Wk + kg * 8 + 4);
                    float xb[4] = {xv.x, xv.y, xv.z, xv.w};
#pragma unroll
                    for (int a = 0; a < 4; a++) {
                        acc[a][0] = fmaf(xb[a], w0.x, acc[a][0]);
                        acc[a][1] = fmaf(xb[a], w0.y, acc[a][1]);
                        acc[a][2] = fmaf(xb[a], w0.z, acc[a][2]);
                        acc[a][3] = fmaf(xb[a], w0.w, acc[a][3]);
                        acc[a][4] = fmaf(xb[a], w1.x, acc[a][4]);
                        acc[a][5] = fmaf(xb[a], w1.y, acc[a][5]);
                    }
                }
                if (c == 7) {   // end of c-part: snapshot n-gate c-accumulator
#pragma unroll
                    for (int a = 0; a < 4; a++) {
                        anc[a][0] = acc[a][4]; anc[a][1] = acc[a][5];
                        acc[a][4] = 0.f; acc[a][5] = 0.f;
                    }
                }
                if (c < 11) {
                    float* dst0 = Xs + ((c + 1) & 1) * 4096;
#pragma unroll
                    for (int j = 0; j < 4; j++) {
                        int kl = lq * 16 + j * 4;
                        float* dst = dst0 + kl * 64 + lb;
                        dst[0] = pf[j].x; dst[64] = pf[j].y;
                        dst[128] = pf[j].z; dst[192] = pf[j].w;
                    }
                }
            }
        }
        __syncthreads();   // Xs free for reduce scratch

        // pack 32 partials, shfl-reduce ks pairs, write to scratch
        {
            float vals[32];
#pragma unroll
            for (int a = 0; a < 4; a++) {
                vals[a*8+0] = acc[a][0]; vals[a*8+1] = acc[a][1];
                vals[a*8+2] = acc[a][2]; vals[a*8+3] = acc[a][3];
                vals[a*8+4] = acc[a][4]; vals[a*8+5] = acc[a][5];
                vals[a*8+6] = anc[a][0]; vals[a*8+7] = anc[a][1];
            }
#pragma unroll
            for (int v = 0; v < 32; v++)
                vals[v] += __shfl_down_sync(0xffffffffu, vals[v], 16);
            if (lane < 16) {
                float* pr = Xs + (wid * 16 + lane) * 32;
#pragma unroll
                for (int v = 0; v < 32; v += 4) {
                    float4 w = {vals[v], vals[v+1], vals[v+2], vals[v+3]};
                    *(float4*)(pr + v) = w;
                }
            }
        }
        __syncthreads();

        if (tid < 128) {
            int b = tid & 63, i = tid >> 6;
            int bgr = b >> 2, bp = b & 3;
            float ar = 0.f, az = 0.f, anh = 0.f, ancv = 0.f;
#pragma unroll
            for (int w = 0; w < 8; w++) {
                const float* p = Xs + (w * 16 + bgr) * 32 + bp * 8;
                ar += p[0 + i]; az += p[2 + i]; anh += p[4 + i]; ancv += p[6 + i];
            }
            int u = blk * 2 + i;
            const float* gi = g_gi_emb + ((size_t)t * Bb + b) * 768;
            float gr = ar + gi[u] + b_hh[u];
            float gz = az + gi[256 + u] + b_hh[256 + u];
            float hn = anh + b_hh[512 + u];
            float gn = ancv + gi[512 + u];
            float r = 1.f / (1.f + expf(-gr));
            float z = 1.f / (1.f + expf(-gz));
            float n = tanhf(gn + r * hn);
            float hp = (t > 0) ? Sprev[(size_t)b * 768 + u] : 0.f;
            g_S[((size_t)t * Bb + b) * 768 + u] = (1.f - z) * n + z * hp;
        }

        bar_target += RB; grid_bar(bar_target);

        // ---- attention: blocks 0..63, block = batch ----
        if (blk < 64) {
            const int b = blk;
            const size_t gbase = ((size_t)t * Bb + b) * 768;
            si_s[tid] = g_S[gbase + tid];
            __syncthreads();
            {
                float sp = 0.f;
                const float4* wa = (const float4*)(W_a + (size_t)tid * 768);
                const float4* sip = (const float4*)si_s;
#pragma unroll 8
                for (int k4 = 0; k4 < 64; k4++) {
                    float4 sv = sip[k4]; float4 w = wa[k4];
                    sp += sv.x * w.x + sv.y * w.y + sv.z * w.z + sv.w * w.w;
                }
                sp_s[tid] = sp;
            }
            __syncthreads();
            if (tid < 128) {
                const float4* hp = (const float4*)(g_hjproj + ((size_t)b * TXx + tid) * Hh);
                const float4* spv = (const float4*)sp_s;
                const float4* vav = (const float4*)va_s;
                float e = 0.f;
#pragma unroll 4
                for (int h4 = 0; h4 < 64; h4++) {
                    float4 h = hp[h4]; float4 s = spv[h4]; float4 v = vav[h4];
                    e += tanh_fast(s.x + h.x) * v.x;
                    e += tanh_fast(s.y + h.y) * v.y;
                    e += tanh_fast(s.z + h.z) * v.z;
                    e += tanh_fast(s.w + h.w) * v.w;
                }
                e_s[tid] = e; red_s[tid] = e;
            }
            __syncthreads();
            for (int st = 64; st > 0; st >>= 1) {
                if (tid < st) red_s[tid] = fmaxf(red_s[tid], red_s[tid + st]);
                __syncthreads();
            }
            float mx = red_s[0];
            __syncthreads();
            if (tid < 128) { float ex = expf(e_s[tid] - mx); e_s[tid] = ex; red_s[tid] = ex; }
            __syncthreads();
            for (int st = 64; st > 0; st >>= 1) {
                if (tid < st) red_s[tid] += red_s[tid + st];
                __syncthreads();
            }
            float inv = 1.f / red_s[0];
            __syncthreads();
            if (tid < 128) e_s[tid] *= inv;
            __syncthreads();

            float c0 = 0.f, c1 = 0.f;
            const float* hjb = h_j + (size_t)b * TXx * 512;
#pragma unroll 8
            for (int tp = 0; tp < 128; tp++) {
                float al = e_s[tp];
                c0 = fmaf(al, hjb[(size_t)tp * 512 + tid], c0);
                c1 = fmaf(al, hjb[(size_t)tp * 512 + 256 + tid], c1);
            }
            g_S[gbase + 256 + tid] = c0;
            g_S[gbase + 512 + tid] = c1;
        }
        bar_target += RB; grid_bar(bar_target);
    }
}

// ---------------------------------------------------------------------------
// fp32 SIMT SGEMM (only for hj_proj)
// ---------------------------------------------------------------------------
__global__ __launch_bounds__(256) void sgemm_nt(
    int M, int N, int K,
    const float* __restrict__ A, int lda,
    const float* __restrict__ B, int ldb,
    float* __restrict__ C)
{
    constexpr int BMs = 128, BNs = 128, BKs = 16;
    __shared__ float As[2][BKs][BMs];
    __shared__ float Bs[2][BKs][BNs];

    const int tid = threadIdx.x;
    const int m0 = blockIdx.x * BMs;
    const int n0 = blockIdx.y * BNs;
    const int tx = tid & 15;
    const int ty = tid >> 4;
    const int lRow = tid >> 1;
    const int lK = (tid & 1) * 8;

    const float* Aptr = A + (size_t)(m0 + lRow) * lda + lK;
    const float* Bptr = B + (size_t)(n0 + lRow) * ldb + lK;

    float acc[8][8];
#pragma unroll
    for (int i = 0; i < 8; i++)
#pragma unroll
        for (int j = 0; j < 8; j++) acc[i][j] = 0.f;

    const int nk = K / BKs;
    float4 ar0, ar1, br0, br1;
    ar0 = *(const float4*)(Aptr);
    ar1 = *(const float4*)(Aptr + 4);
    br0 = *(const float4*)(Bptr);
    br1 = *(const float4*)(Bptr + 4);
#pragma unroll
    for (int q = 0; q < 4; q++) {
        As[0][lK + q][lRow] = ((const float*)&ar0)[q];
        As[0][lK + 4 + q][lRow] = ((const float*)&ar1)[q];
        Bs[0][lK + q][lRow] = ((const float*)&br0)[q];
        Bs[0][lK + 4 + q][lRow] = ((const float*)&br1)[q];
    }
    __syncthreads();

    for (int kt = 0; kt < nk; kt++) {
        const int cur = kt & 1;
        const bool has_next = (kt + 1 < nk);
        if (has_next) {
            const float* Ap = Aptr + (kt + 1) * BKs;
            const float* Bp = Bptr + (kt + 1) * BKs;
            ar0 = *(const float4*)(Ap);
            ar1 = *(const float4*)(Ap + 4);
            br0 = *(const float4*)(Bp);
            br1 = *(const float4*)(Bp + 4);
        }
#pragma unroll
        for (int kk = 0; kk < BKs; kk++) {
            float4 a0 = *(const float4*)&As[cur][kk][ty * 8];
            float4 a1 = *(const float4*)&As[cur][kk][ty * 8 + 4];
            float4 b0 = *(const float4*)&Bs[cur][kk][tx * 8];
            float4 b1 = *(const float4*)&Bs[cur][kk][tx * 8 + 4];
            float av[8] = {a0.x, a0.y, a0.z, a0.w, a1.x, a1.y, a1.z, a1.w};
            float bv[8] = {b0.x, b0.y, b0.z, b0.w, b1.x, b1.y, b1.z, b1.w};
#pragma unroll
            for (int i = 0; i < 8; i++)
#pragma unroll
                for (int j = 0; j < 8; j++)
                    acc[i][j] = fmaf(av[i], bv[j], acc[i][j]);
        }
        if (has_next) {
            const int nxt = cur ^ 1;
#pragma unroll
            for (int q = 0; q < 4; q++) {
                As[nxt][lK + q][lRow] = ((const float*)&ar0)[q];
                As[nxt][lK + 4 + q][lRow] = ((const float*)&ar1)[q];
                Bs[nxt][lK + q][lRow] = ((const float*)&br0)[q];
                Bs[nxt][lK + 4 + q][lRow] = ((const float*)&br1)[q];
            }
            __syncthreads();
        }
    }
#pragma unroll
    for (int i = 0; i < 8; i++) {
        float* crow = C + (size_t)(m0 + ty * 8 + i) * N + n0 + tx * 8;
        float4 v0 = {acc[i][0], acc[i][1], acc[i][2], acc[i][3]};
        float4 v1 = {acc[i][4], acc[i][5], acc[i][6], acc[i][7]};
        *(float4*)(crow) = v0;
        *(float4*)(crow + 4) = v1;
    }
}

// ---------------------------------------------------------------------------
// conv_W: W_mo (fp32, interleave-reordered rows) -> g_B2 bf16 split tiles.
// Terms along K: 0 = hi, 1 = lo, 2 = hi.
// ---------------------------------------------------------------------------
__global__ __launch_bounds__(128) void conv_W_kernel(const float* __restrict__ W_mo)
{
    const int kb = blockIdx.x, nt = blockIdx.y;
    const int r = threadIdx.x;
    const int n = nt * 128 + r;
    const int wrow = (n & 1) * Vv + (n >> 1);
    const int term = kb / 12;
    const int kk0 = (kb % 12) * 64;
    const float* src = W_mo + (size_t)wrow * 768 + kk0;
    char* tile = (char*)g_B2 + (size_t)(nt * NKB + kb) * KTILE_BYTES;

#pragma unroll
    for (int j = 0; j < 8; j++) {
        float4 x0 = *(const float4*)(src + j * 8);
        float4 x1 = *(const float4*)(src + j * 8 + 4);
        float xs[8] = {x0.x, x0.y, x0.z, x0.w, x1.x, x1.y, x1.z, x1.w};
        unsigned short o[8];
#pragma unroll
        for (int q = 0; q < 8; q++) {
            __nv_bfloat16 h = __float2bfloat16(xs[q]);
            if (term == 1) h = __float2bfloat16(xs[q] - __bfloat162float(h));
            o[q] = *(unsigned short*)&h;
        }
        uint32_t off = sw128((uint32_t)r * 128 + j * 16);
        *(uint4*)(tile + off) = *(uint4*)o;
    }
}

// conv_S: g_S (fp32 [4096][768]) -> g_A2. Terms: 0 = hi, 1 = hi, 2 = lo.
__global__ __launch_bounds__(128) void conv_S_kernel()
{
    const int kb = blockIdx.x, mt = blockIdx.y;
    const int r = threadIdx.x;
    const int m = mt * 128 + r;
    const int term = kb / 12;
    const int kk0 = (kb % 12) * 64;
    const float* src = g_S + (size_t)m * 768 + kk0;
    char* tile = (char*)g_A2 + (size_t)(mt * NKB + kb) * KTILE_BYTES;

#pragma unroll
    for (int j = 0; j < 8; j++) {
        float4 x0 = *(const float4*)(src + j * 8);
        float4 x1 = *(const float4*)(src + j * 8 + 4);
        float xs[8] = {x0.x, x0.y, x0.z, x0.w, x1.x, x1.y, x1.z, x1.w};
        unsigned short o[8];
#pragma unroll
        for (int q = 0; q < 8; q++) {
            __nv_bfloat16 h = __float2bfloat16(xs[q]);
            if (term == 2) h = __float2bfloat16(xs[q] - __bfloat162float(h));
            o[q] = *(unsigned short*)&h;
        }
        uint32_t off = sw128((uint32_t)r * 128 + j * 16);
        *(uint4*)(tile + off) = *(uint4*)o;
    }
}

// ---------------------------------------------------------------------------
// mma.sync bf16 GEMM. CTA 128x128x64, 256 threads, 8 warps (4x2),
// warp tile 32x64, 3-stage cp.async. Fused pair-max + bias epilogue.
// ---------------------------------------------------------------------------
__global__ __launch_bounds__(256) void gemm_mma_kernel(
    float* __restrict__ out, const float* __restrict__ b_mo)
{
    extern __shared__ char dsm[];
    const uint32_t sbase = (smem_u32(dsm) + 127) & ~127u;

    const int tid = threadIdx.x;
    const int lane = tid & 31;
    const int wid = tid >> 5;
    const int wm = (wid & 3) * 32;
    const int wn = (wid >> 2) * 64;
    const int mt = blockIdx.x, nt = blockIdx.y;

    const char* Ab = (const char*)g_A2 + (size_t)mt * NKB * KTILE_BYTES;
    const char* Bbp = (const char*)g_B2 + (size_t)nt * NKB * KTILE_BYTES;

    auto load_stage = [&](int kb, int s) {
        uint32_t sa = sbase + s * STAGE_BYTES + tid * 16;
        const char* ga = Ab + (size_t)kb * KTILE_BYTES + tid * 16;
        const char* gb = Bbp + (size_t)kb * KTILE_BYTES + tid * 16;
#pragma unroll
        for (int i = 0; i < 4; i++) cp_async16(sa + i * 4096, ga + i * 4096);
        sa += 16384;
#pragma unroll
        for (int i = 0; i < 4; i++) cp_async16(sa + i * 4096, gb + i * 4096);
        cp_commit();
    };

    float acc[2][8][4];
#pragma unroll
    for (int i = 0; i < 2; i++)
#pragma unroll
        for (int j = 0; j < 8; j++)
#pragma unroll
            for (int q = 0; q < 4; q++) acc[i][j][q] = 0.f;

    load_stage(0, 0);
    load_stage(1, 1);

    const uint32_t a_row = wm + (lane & 15);
    const uint32_t a_kb  = (lane >> 4) * 16;
    const uint32_t b_row = wn + (lane & 7) + ((lane >> 4) << 3);
    const uint32_t b_kb  = ((lane >> 3) & 1) * 16;

    for (int kb = 0; kb < NKB; kb++) {
        const int s = kb % NSTAGE;
        if (kb >= NKB - 1) asm volatile("cp.async.wait_group 0;" ::: "memory");
        else               asm volatile("cp.async.wait_group 1;" ::: "memory");
        __syncthreads();

        const uint32_t abase = sbase + s * STAGE_BYTES;
        const uint32_t bbase = abase + 16384;

#pragma unroll
        for (int ks = 0; ks < 4; ks++) {
            uint32_t afr[2][4];
#pragma unroll
            for (int i = 0; i < 2; i++) {
                uint32_t ad = abase + sw128((a_row + i * 16) * 128 + ks * 32 + a_kb);
                ldsm4(afr[i], ad);
            }
            uint32_t bfr[4][4];
#pragma unroll
            for (int j = 0; j < 4; j++) {
                uint32_t bd = bbase + sw128((b_row + j * 16) * 128 + ks * 32 + b_kb);
                ldsm4(bfr[j], bd);
            }
#pragma unroll
            for (int i = 0; i < 2; i++)
#pragma unroll
                for (int j = 0; j < 8; j++) {
                    uint32_t b0 = bfr[j >> 1][(j & 1) * 2];
                    uint32_t b1 = bfr[j >> 1][(j & 1) * 2 + 1];
                    mma16816(acc[i][j], afr[i], b0, b1);
                }
        }

        const int nxt = kb + 2;
        if (nxt < NKB) load_stage(nxt, nxt % NSTAGE);
    }

#pragma unroll
    for (int i = 0; i < 2; i++) {
        int mrow0 = mt * 128 + wm + i * 16 + (lane >> 2);
        int mrow1 = mrow0 + 8;
        int t0 = mrow0 >> 6, bb0 = mrow0 & 63;
        int t1 = mrow1 >> 6, bb1 = mrow1 & 63;
        float* orow0 = out + (size_t)bb0 * (TYy * Vv) + (size_t)t0 * Vv;
        float* orow1 = out + (size_t)bb1 * (TYy * Vv) + (size_t)t1 * Vv;
#pragma unroll
        for (int j = 0; j < 8; j++) {
            int ncol = nt * 128 + wn + j * 8 + (lane & 3) * 2;
            int p = ncol >> 1;
            float be = b_mo[p], bo = b_mo[Vv + p];
            orow0[p] = fmaxf(acc[i][j][0] + be, acc[i][j][1] + bo);
            orow1[p] = fmaxf(acc[i][j][2] + be, acc[i][j][3] + bo);
        }
    }
}

// ---------------------------------------------------------------------------
extern "C" void kernel_launch(void* const* d_in, const int* in_sizes, int n_in,
                              void* d_out, int out_size)
{
    const int*   y    = (const int*)d_in[0];
    const float* h_j  = (const float*)d_in[1];
    const float* emb  = (const float*)d_in[2];
    const float* W_ih = (const float*)d_in[3];
    const float* W_hh = (const float*)d_in[4];
    const float* b_ih = (const float*)d_in[5];
    const float* b_hh = (const float*)d_in[6];
    const float* W_a  = (const float*)d_in[7];
    const float* v_a  = (const float*)d_in[8];
    const float* W_mo = (const float*)d_in[9];
    const float* b_mo = (const float*)d_in[10];
    float* out = (float*)d_out;

    void* hjp_v; cudaGetSymbolAddress(&hjp_v, g_hjproj);
    float* hjp = (float*)hjp_v;

    const int smem_bytes = NSTAGE * STAGE_BYTES + 128;
    cudaFuncSetAttribute(gemm_mma_kernel,
                         cudaFuncAttributeMaxDynamicSharedMemorySize, smem_bytes);
    const int recur_smem = 15360 * 4;   // 61,440 B
    cudaFuncSetAttribute(recur_kernel,
                         cudaFuncAttributeMaxDynamicSharedMemorySize, recur_smem);

    // W_mo -> bf16 split tiles (independent of recurrence)
    conv_W_kernel<<<dim3(NKB, 500), 128>>>(W_mo);

    // hj_proj: (B*TX, 512) @ W_a[:,256:768]^T
    sgemm_nt<<<dim3((Bb * TXx) / 128, Hh / 128), 256>>>(
        Bb * TXx, Hh, 2 * Hh, h_j, 2 * Hh, W_a + Hh, 3 * Hh, hjp);

    emb_gemm_kernel<<<(TYy * Bb) / 16, 256>>>(y, emb, W_ih, b_ih);

    // persistent recurrence (barrier counter reset first, every replay)
    reset_bar_kernel<<<1, 1>>>();
    recur_kernel<<<RB, 256, recur_smem>>>(h_j, W_ih, W_hh, b_hh, W_a, v_a);

    // S -> bf16 split tiles, then HMMA GEMM with fused max epilogue
    conv_S_kernel<<<dim3(NKB, 32), 128>>>();
    gemm_mma_kernel<<<dim3(32, 500), 256, smem_bytes>>>(out, b_mo);
}

// round 14
// speedup vs baseline: 3.5215x; 1.1963x over previous
#include <cuda_runtime.h>
#include <cuda_fp16.h>
#include <math.h>
#include <stdint.h>

#define Vv 32000
#define Ee 128
#define Hh 256
#define Bb 64
#define TYy 64
#define TXx 128

#define NKB 24             // K-blocks of 64 fp16: [Shi|Shi] x [Whi|Wlo], K_eff=1536
#define NKA 12             // distinct A K-blocks (A halves identical)
#define KTILE_BYTES 16384  // 128 rows x 64 fp16 (swizzled)
#define STAGE_BYTES 32768  // A tile + B tile
#define NSTAGE 3
#define RB 128             // recurrence blocks

// Scratch (device globals — no allocation allowed)
__device__ float g_hjproj[Bb * TXx * Hh];
__device__ float g_gi_emb[TYy * Bb * 768];
__device__ float g_S[TYy * Bb * 768];   // [t][b]{ s_i(256), c_new(512) }
__device__ unsigned g_bar_ctr;
// fp16-split tiled operands for the big GEMM (pre-swizzled 128x64 tiles)
__device__ __align__(128) unsigned short g_A2[32 * NKA * 8192];    // 32 m-tiles
__device__ __align__(128) unsigned short g_B2[500 * NKB * 8192];   // 500 n-tiles

__device__ __forceinline__ float tanh_fast(float x) {
    float y; asm("tanh.approx.f32 %0, %1;" : "=f"(y) : "f"(x)); return y;
}
__device__ __forceinline__ uint32_t smem_u32(const void* p) {
    uint32_t a;
    asm("{ .reg .u64 t; cvta.to.shared.u64 t, %1; cvt.u32.u64 %0, t; }" : "=r"(a) : "l"(p));
    return a;
}
__device__ __forceinline__ uint32_t sw128(uint32_t off) { return off ^ ((off >> 3) & 0x70); }

__device__ __forceinline__ void cp_async16(uint32_t saddr, const void* g) {
    asm volatile("cp.async.cg.shared.global [%0], [%1], 16;" :: "r"(saddr), "l"(g));
}
__device__ __forceinline__ void cp_commit() { asm volatile("cp.async.commit_group;"); }

__device__ __forceinline__ void ldsm4(uint32_t* r, uint32_t addr) {
    asm volatile("ldmatrix.sync.aligned.m8n8.x4.shared.b16 {%0,%1,%2,%3}, [%4];"
                 : "=r"(r[0]), "=r"(r[1]), "=r"(r[2]), "=r"(r[3]) : "r"(addr));
}
__device__ __forceinline__ void mma16816(float* d, const uint32_t* a, uint32_t b0, uint32_t b1) {
    asm volatile("mma.sync.aligned.m16n8k16.row.col.f32.f16.f16.f32 "
                 "{%0,%1,%2,%3}, {%4,%5,%6,%7}, {%8,%9}, {%0,%1,%2,%3};"
                 : "+f"(d[0]), "+f"(d[1]), "+f"(d[2]), "+f"(d[3])
                 : "r"(a[0]), "r"(a[1]), "r"(a[2]), "r"(a[3]), "r"(b0), "r"(b1));
}

__global__ void reset_bar_kernel() { g_bar_ctr = 0; }

__device__ __forceinline__ void grid_bar(unsigned target) {
    __syncthreads();
    if (threadIdx.x == 0) {
        __threadfence();
        atomicAdd(&g_bar_ctr, 1u);
        while (*(volatile unsigned*)&g_bar_ctr < target) { }
        __threadfence();
    }
    __syncthreads();
}

// ---------------------------------------------------------------------------
// K1: gi_emb = b_ih + emb_eff[y] @ W_ih[:, :128].T
// ---------------------------------------------------------------------------
__global__ __launch_bounds__(256) void emb_gemm_kernel(
    const int* __restrict__ y, const float* __restrict__ emb,
    const float* __restrict__ W_ih, const float* __restrict__ b_ih)
{
    __shared__ float Xs[16][128];
    const int tid = threadIdx.x;
    const int m_base = blockIdx.x * 16;

    for (int idx = tid; idx < 16 * 128; idx += 256) {
        int i = idx >> 7, k = idx & 127;
        int m = m_base + i;
        int tt = m >> 6, bb = m & 63;
        int yv = y[bb * TYy + tt];
        Xs[i][k] = (yv == 0) ? 0.f : emb[(size_t)yv * Ee + k];
    }
    __syncthreads();

    float acc0[16], acc1[16], acc2[16];
#pragma unroll
    for (int i = 0; i < 16; i++) { acc0[i] = 0.f; acc1[i] = 0.f; acc2[i] = 0.f; }

    const float* w0 = W_ih + (size_t)tid * 640;
    const float* w1 = W_ih + (size_t)(tid + 256) * 640;
    const float* w2 = W_ih + (size_t)(tid + 512) * 640;

    for (int k = 0; k < 128; k++) {
        float a = w0[k], b = w1[k], c = w2[k];
#pragma unroll
        for (int i = 0; i < 16; i++) {
            float x = Xs[i][k];
            acc0[i] = fmaf(x, a, acc0[i]);
            acc1[i] = fmaf(x, b, acc1[i]);
            acc2[i] = fmaf(x, c, acc2[i]);
        }
    }
    float bi0 = b_ih[tid], bi1 = b_ih[tid + 256], bi2 = b_ih[tid + 512];
#pragma unroll
    for (int i = 0; i < 16; i++) {
        size_t base = (size_t)(m_base + i) * 768;
        g_gi_emb[base + tid]       = acc0[i] + bi0;
        g_gi_emb[base + tid + 256] = acc1[i] + bi1;
        g_gi_emb[base + tid + 512] = acc2[i] + bi2;
    }
}

// ---------------------------------------------------------------------------
// Persistent recurrence kernel: 128 blocks x 256 threads, custom grid barrier.
// ---------------------------------------------------------------------------
__global__ __launch_bounds__(256, 1) void recur_kernel(
    const float* __restrict__ h_j, const float* __restrict__ W_ih,
    const float* __restrict__ W_hh, const float* __restrict__ b_hh,
    const float* __restrict__ W_a, const float* __restrict__ v_a)
{
    extern __shared__ float sm[];
    float* Wk   = sm;              // [768][8]
    float* Xs   = sm + 6144;       // [2][64][64]
    float* si_s = sm + 14336;
    float* sp_s = si_s + 256;
    float* va_s = sp_s + 256;
    float* e_s  = va_s + 256;
    float* red_s = e_s + 128;

    const int tid = threadIdx.x;
    const int blk = blockIdx.x;
    const int bg = tid & 15, ks = tid >> 4;
    const int wid = tid >> 5, lane = tid & 31;
    const int lb = tid & 63, lq = tid >> 6;

    for (int r = 0; r < 6; r++) {
        int g = r >> 1, i = r & 1;
        int row = g * 256 + blk * 2 + i;
        const float* wih = W_ih + (size_t)row * 640 + 128;
        const float* whh = W_hh + (size_t)row * 256;
        for (int k = tid; k < 768; k += 256)
            Wk[k * 8 + r] = (k < 512) ? wih[k] : whh[k - 512];
    }
    for (int k = tid; k < 768; k += 256) { Wk[k * 8 + 6] = 0.f; Wk[k * 8 + 7] = 0.f; }
    va_s[tid] = v_a[tid];

    unsigned bar_target = 0;

    for (int t = 0; t < TYy; t++) {
        const float* Sprev = g_S + (size_t)(t - 1) * Bb * 768;

        float acc[4][6], anc[4][2];
#pragma unroll
        for (int a = 0; a < 4; a++) {
#pragma unroll
            for (int r = 0; r < 6; r++) acc[a][r] = 0.f;
            anc[a][0] = 0.f; anc[a][1] = 0.f;
        }

        if (t > 0) {
            const float* srow = Sprev + (size_t)lb * 768;
#pragma unroll
            for (int j = 0; j < 4; j++) {
                int kl = lq * 16 + j * 4;
                float4 v = *(const float4*)(srow + 256 + kl);
                float* dst = Xs + kl * 64 + lb;
                dst[0] = v.x; dst[64] = v.y; dst[128] = v.z; dst[192] = v.w;
            }
            for (int c = 0; c < 12; c++) {
                __syncthreads();
                float4 pf[4];
                if (c < 11) {
                    int cn = c + 1;
                    int base = (cn < 8) ? (256 + cn * 64) : (cn * 64 - 512);
#pragma unroll
                    for (int j = 0; j < 4; j++)
                        pf[j] = *(const float4*)(srow + base + lq * 16 + j * 4);
                }
                const float* XB = Xs + (c & 1) * 4096;
#pragma unroll
                for (int kq = 0; kq < 4; kq++) {
                    int kl = ks * 4 + kq;
                    int kg = c * 64 + kl;
                    float4 xv = *(const float4*)(XB + kl * 64 + bg * 4);
                    float4 w0 = *(const float4*)(Wk + kg * 8);
                    float4 w1 = *(const float4*)(Wk + kg * 8 + 4);
                    float xb[4] = {xv.x, xv.y, xv.z, xv.w};
#pragma unroll
                    for (int a = 0; a < 4; a++) {
                        acc[a][0] = fmaf(xb[a], w0.x, acc[a][0]);
                        acc[a][1] = fmaf(xb[a], w0.y, acc[a][1]);
                        acc[a][2] = fmaf(xb[a], w0.z, acc[a][2]);
                        acc[a][3] = fmaf(xb[a], w0.w, acc[a][3]);
                        acc[a][4] = fmaf(xb[a], w1.x, acc[a][4]);
                        acc[a][5] = fmaf(xb[a], w1.y, acc[a][5]);
                    }
                }
                if (c == 7) {
#pragma unroll
                    for (int a = 0; a < 4; a++) {
                        anc[a][0] = acc[a][4]; anc[a][1] = acc[a][5];
                        acc[a][4] = 0.f; acc[a][5] = 0.f;
                    }
                }
                if (c < 11) {
                    float* dst0 = Xs + ((c + 1) & 1) * 4096;
#pragma unroll
                    for (int j = 0; j < 4; j++) {
                        int kl = lq * 16 + j * 4;
                        float* dst = dst0 + kl * 64 + lb;
                        dst[0] = pf[j].x; dst[64] = pf[j].y;
                        dst[128] = pf[j].z; dst[192] = pf[j].w;
                    }
                }
            }
        }
        __syncthreads();

        {
            float vals[32];
#pragma unroll
            for (int a = 0; a < 4; a++) {
                vals[a*8+0] = acc[a][0]; vals[a*8+1] = acc[a][1];
                vals[a*8+2] = acc[a][2]; vals[a*8+3] = acc[a][3];
                vals[a*8+4] = acc[a][4]; vals[a*8+5] = acc[a][5];
                vals[a*8+6] = anc[a][0]; vals[a*8+7] = anc[a][1];
            }
#pragma unroll
            for (int v = 0; v < 32; v++)
                vals[v] += __shfl_down_sync(0xffffffffu, vals[v], 16);
            if (lane < 16) {
                float* pr = Xs + (wid * 16 + lane) * 32;
#pragma unroll
                for (int v = 0; v < 32; v += 4) {
                    float4 w = {vals[v], vals[v+1], vals[v+2], vals[v+3]};
                    *(float4*)(pr + v) = w;
                }
            }
        }
        __syncthreads();

        if (tid < 128) {
            int b = tid & 63, i = tid >> 6;
            int bgr = b >> 2, bp = b & 3;
            float ar = 0.f, az = 0.f, anh = 0.f, ancv = 0.f;
#pragma unroll
            for (int w = 0; w < 8; w++) {
                const float* p = Xs + (w * 16 + bgr) * 32 + bp * 8;
                ar += p[0 + i]; az += p[2 + i]; anh += p[4 + i]; ancv += p[6 + i];
            }
            int u = blk * 2 + i;
            const float* gi = g_gi_emb + ((size_t)t * Bb + b) * 768;
            float gr = ar + gi[u] + b_hh[u];
            float gz = az + gi[256 + u] + b_hh[256 + u];
            float hn = anh + b_hh[512 + u];
            float gn = ancv + gi[512 + u];
            float r = 1.f / (1.f + expf(-gr));
            float z = 1.f / (1.f + expf(-gz));
            float n = tanhf(gn + r * hn);
            float hp = (t > 0) ? Sprev[(size_t)b * 768 + u] : 0.f;
            g_S[((size_t)t * Bb + b) * 768 + u] = (1.f - z) * n + z * hp;
        }

        bar_target += RB; grid_bar(bar_target);

        if (blk < 64) {
            const int b = blk;
            const size_t gbase = ((size_t)t * Bb + b) * 768;
            si_s[tid] = g_S[gbase + tid];
            __syncthreads();
            {
                float sp = 0.f;
                const float4* wa = (const float4*)(W_a + (size_t)tid * 768);
                const float4* sip = (const float4*)si_s;
#pragma unroll 8
                for (int k4 = 0; k4 < 64; k4++) {
                    float4 sv = sip[k4]; float4 w = wa[k4];
                    sp += sv.x * w.x + sv.y * w.y + sv.z * w.z + sv.w * w.w;
                }
                sp_s[tid] = sp;
            }
            __syncthreads();
            if (tid < 128) {
                const float4* hp = (const float4*)(g_hjproj + ((size_t)b * TXx + tid) * Hh);
                const float4* spv = (const float4*)sp_s;
                const float4* vav = (const float4*)va_s;
                float e = 0.f;
#pragma unroll 4
                for (int h4 = 0; h4 < 64; h4++) {
                    float4 h = hp[h4]; float4 s = spv[h4]; float4 v = vav[h4];
                    e += tanh_fast(s.x + h.x) * v.x;
                    e += tanh_fast(s.y + h.y) * v.y;
                    e += tanh_fast(s.z + h.z) * v.z;
                    e += tanh_fast(s.w + h.w) * v.w;
                }
                e_s[tid] = e; red_s[tid] = e;
            }
            __syncthreads();
            for (int st = 64; st > 0; st >>= 1) {
                if (tid < st) red_s[tid] = fmaxf(red_s[tid], red_s[tid + st]);
                __syncthreads();
            }
            float mx = red_s[0];
            __syncthreads();
            if (tid < 128) { float ex = expf(e_s[tid] - mx); e_s[tid] = ex; red_s[tid] = ex; }
            __syncthreads();
            for (int st = 64; st > 0; st >>= 1) {
                if (tid < st) red_s[tid] += red_s[tid + st];
                __syncthreads();
            }
            float inv = 1.f / red_s[0];
            __syncthreads();
            if (tid < 128) e_s[tid] *= inv;
            __syncthreads();

            float c0 = 0.f, c1 = 0.f;
            const float* hjb = h_j + (size_t)b * TXx * 512;
#pragma unroll 8
            for (int tp = 0; tp < 128; tp++) {
                float al = e_s[tp];
                c0 = fmaf(al, hjb[(size_t)tp * 512 + tid], c0);
                c1 = fmaf(al, hjb[(size_t)tp * 512 + 256 + tid], c1);
            }
            g_S[gbase + 256 + tid] = c0;
            g_S[gbase + 512 + tid] = c1;
        }
        bar_target += RB; grid_bar(bar_target);
    }
}

// ---------------------------------------------------------------------------
// fp32 SIMT SGEMM (only for hj_proj)
// ---------------------------------------------------------------------------
__global__ __launch_bounds__(256) void sgemm_nt(
    int M, int N, int K,
    const float* __restrict__ A, int lda,
    const float* __restrict__ B, int ldb,
    float* __restrict__ C)
{
    constexpr int BMs = 128, BNs = 128, BKs = 16;
    __shared__ float As[2][BKs][BMs];
    __shared__ float Bs[2][BKs][BNs];

    const int tid = threadIdx.x;
    const int m0 = blockIdx.x * BMs;
    const int n0 = blockIdx.y * BNs;
    const int tx = tid & 15;
    const int ty = tid >> 4;
    const int lRow = tid >> 1;
    const int lK = (tid & 1) * 8;

    const float* Aptr = A + (size_t)(m0 + lRow) * lda + lK;
    const float* Bptr = B + (size_t)(n0 + lRow) * ldb + lK;

    float acc[8][8];
#pragma unroll
    for (int i = 0; i < 8; i++)
#pragma unroll
        for (int j = 0; j < 8; j++) acc[i][j] = 0.f;

    const int nk = K / BKs;
    float4 ar0, ar1, br0, br1;
    ar0 = *(const float4*)(Aptr);
    ar1 = *(const float4*)(Aptr + 4);
    br0 = *(const float4*)(Bptr);
    br1 = *(const float4*)(Bptr + 4);
#pragma unroll
    for (int q = 0; q < 4; q++) {
        As[0][lK + q][lRow] = ((const float*)&ar0)[q];
        As[0][lK + 4 + q][lRow] = ((const float*)&ar1)[q];
        Bs[0][lK + q][lRow] = ((const float*)&br0)[q];
        Bs[0][lK + 4 + q][lRow] = ((const float*)&br1)[q];
    }
    __syncthreads();

    for (int kt = 0; kt < nk; kt++) {
        const int cur = kt & 1;
        const bool has_next = (kt + 1 < nk);
        if (has_next) {
            const float* Ap = Aptr + (kt + 1) * BKs;
            const float* Bp = Bptr + (kt + 1) * BKs;
            ar0 = *(const float4*)(Ap);
            ar1 = *(const float4*)(Ap + 4);
            br0 = *(const float4*)(Bp);
            br1 = *(const float4*)(Bp + 4);
        }
#pragma unroll
        for (int kk = 0; kk < BKs; kk++) {
            float4 a0 = *(const float4*)&As[cur][kk][ty * 8];
            float4 a1 = *(const float4*)&As[cur][kk][ty * 8 + 4];
            float4 b0 = *(const float4*)&Bs[cur][kk][tx * 8];
            float4 b1 = *(const float4*)&Bs[cur][kk][tx * 8 + 4];
            float av[8] = {a0.x, a0.y, a0.z, a0.w, a1.x, a1.y, a1.z, a1.w};
            float bv[8] = {b0.x, b0.y, b0.z, b0.w, b1.x, b1.y, b1.z, b1.w};
#pragma unroll
            for (int i = 0; i < 8; i++)
#pragma unroll
                for (int j = 0; j < 8; j++)
                    acc[i][j] = fmaf(av[i], bv[j], acc[i][j]);
        }
        if (has_next) {
            const int nxt = cur ^ 1;
#pragma unroll
            for (int q = 0; q < 4; q++) {
                As[nxt][lK + q][lRow] = ((const float*)&ar0)[q];
                As[nxt][lK + 4 + q][lRow] = ((const float*)&ar1)[q];
                Bs[nxt][lK + q][lRow] = ((const float*)&br0)[q];
                Bs[nxt][lK + 4 + q][lRow] = ((const float*)&br1)[q];
            }
            __syncthreads();
        }
    }
#pragma unroll
    for (int i = 0; i < 8; i++) {
        float* crow = C + (size_t)(m0 + ty * 8 + i) * N + n0 + tx * 8;
        float4 v0 = {acc[i][0], acc[i][1], acc[i][2], acc[i][3]};
        float4 v1 = {acc[i][4], acc[i][5], acc[i][6], acc[i][7]};
        *(float4*)(crow) = v0;
        *(float4*)(crow + 4) = v1;
    }
}

// ---------------------------------------------------------------------------
// conv_W: W_mo (fp32, interleave-reordered rows) -> g_B2 fp16 split tiles.
// Terms along K: kb/12 == 0 -> hi, == 1 -> lo.
// ---------------------------------------------------------------------------
__global__ __launch_bounds__(128) void conv_W_kernel(const float* __restrict__ W_mo)
{
    const int kb = blockIdx.x, nt = blockIdx.y;
    const int r = threadIdx.x;
    const int n = nt * 128 + r;
    const int wrow = (n & 1) * Vv + (n >> 1);
    const int term = kb / 12;
    const int kk0 = (kb % 12) * 64;
    const float* src = W_mo + (size_t)wrow * 768 + kk0;
    char* tile = (char*)g_B2 + (size_t)(nt * NKB + kb) * KTILE_BYTES;

#pragma unroll
    for (int j = 0; j < 8; j++) {
        float4 x0 = *(const float4*)(src + j * 8);
        float4 x1 = *(const float4*)(src + j * 8 + 4);
        float xs[8] = {x0.x, x0.y, x0.z, x0.w, x1.x, x1.y, x1.z, x1.w};
        unsigned short o[8];
#pragma unroll
        for (int q = 0; q < 8; q++) {
            __half h = __float2half_rn(xs[q]);
            if (term == 1) h = __float2half_rn(xs[q] - __half2float(h));
            o[q] = *(unsigned short*)&h;
        }
        uint32_t off = sw128((uint32_t)r * 128 + j * 16);
        *(uint4*)(tile + off) = *(uint4*)o;
    }
}

// conv_S: g_S (fp32 [4096][768]) -> g_A2 fp16 hi tiles (12 K-blocks only).
__global__ __launch_bounds__(128) void conv_S_kernel()
{
    const int kb = blockIdx.x, mt = blockIdx.y;
    const int r = threadIdx.x;
    const int m = mt * 128 + r;
    const int kk0 = kb * 64;
    const float* src = g_S + (size_t)m * 768 + kk0;
    char* tile = (char*)g_A2 + (size_t)(mt * NKA + kb) * KTILE_BYTES;

#pragma unroll
    for (int j = 0; j < 8; j++) {
        float4 x0 = *(const float4*)(src + j * 8);
        float4 x1 = *(const float4*)(src + j * 8 + 4);
        float xs[8] = {x0.x, x0.y, x0.z, x0.w, x1.x, x1.y, x1.z, x1.w};
        unsigned short o[8];
#pragma unroll
        for (int q = 0; q < 8; q++) {
            __half h = __float2half_rn(xs[q]);
            o[q] = *(unsigned short*)&h;
        }
        uint32_t off = sw128((uint32_t)r * 128 + j * 16);
        *(uint4*)(tile + off) = *(uint4*)o;
    }
}

// ---------------------------------------------------------------------------
// mma.sync fp16 GEMM. CTA 128x128x64, 256 threads, 8 warps (4x2),
// warp tile 32x64, 3-stage cp.async. A K-blocks repeat (kb % 12).
// Fused pair-max + bias epilogue.
// ---------------------------------------------------------------------------
__global__ __launch_bounds__(256) void gemm_mma_kernel(
    float* __restrict__ out, const float* __restrict__ b_mo)
{
    extern __shared__ char dsm[];
    const uint32_t sbase = (smem_u32(dsm) + 127) & ~127u;

    const int tid = threadIdx.x;
    const int lane = tid & 31;
    const int wid = tid >> 5;
    const int wm = (wid & 3) * 32;
    const int wn = (wid >> 2) * 64;
    const int mt = blockIdx.x, nt = blockIdx.y;

    const char* Ab = (const char*)g_A2 + (size_t)mt * NKA * KTILE_BYTES;
    const char* Bbp = (const char*)g_B2 + (size_t)nt * NKB * KTILE_BYTES;

    auto load_stage = [&](int kb, int s) {
        uint32_t sa = sbase + s * STAGE_BYTES + tid * 16;
        const char* ga = Ab + (size_t)(kb % NKA) * KTILE_BYTES + tid * 16;
        const char* gb = Bbp + (size_t)kb * KTILE_BYTES + tid * 16;
#pragma unroll
        for (int i = 0; i < 4; i++) cp_async16(sa + i * 4096, ga + i * 4096);
        sa += 16384;
#pragma unroll
        for (int i = 0; i < 4; i++) cp_async16(sa + i * 4096, gb + i * 4096);
        cp_commit();
    };

    float acc[2][8][4];
#pragma unroll
    for (int i = 0; i < 2; i++)
#pragma unroll
        for (int j = 0; j < 8; j++)
#pragma unroll
            for (int q = 0; q < 4; q++) acc[i][j][q] = 0.f;

    load_stage(0, 0);
    load_stage(1, 1);

    const uint32_t a_row = wm + (lane & 15);
    const uint32_t a_kb  = (lane >> 4) * 16;
    const uint32_t b_row = wn + (lane & 7) + ((lane >> 4) << 3);
    const uint32_t b_kb  = ((lane >> 3) & 1) * 16;

    for (int kb = 0; kb < NKB; kb++) {
        const int s = kb % NSTAGE;
        if (kb >= NKB - 1) asm volatile("cp.async.wait_group 0;" ::: "memory");
        else               asm volatile("cp.async.wait_group 1;" ::: "memory");
        __syncthreads();

        const uint32_t abase = sbase + s * STAGE_BYTES;
        const uint32_t bbase = abase + 16384;

#pragma unroll
        for (int ks = 0; ks < 4; ks++) {
            uint32_t afr[2][4];
#pragma unroll
            for (int i = 0; i < 2; i++) {
                uint32_t ad = abase + sw128((a_row + i * 16) * 128 + ks * 32 + a_kb);
                ldsm4(afr[i], ad);
            }
            uint32_t bfr[4][4];
#pragma unroll
            for (int j = 0; j < 4; j++) {
                uint32_t bd = bbase + sw128((b_row + j * 16) * 128 + ks * 32 + b_kb);
                ldsm4(bfr[j], bd);
            }
#pragma unroll
            for (int i = 0; i < 2; i++)
#pragma unroll
                for (int j = 0; j < 8; j++) {
                    uint32_t b0 = bfr[j >> 1][(j & 1) * 2];
                    uint32_t b1 = bfr[j >> 1][(j & 1) * 2 + 1];
                    mma16816(acc[i][j], afr[i], b0, b1);
                }
        }

        const int nxt = kb + 2;
        if (nxt < NKB) load_stage(nxt, nxt % NSTAGE);
    }

#pragma unroll
    for (int i = 0; i < 2; i++) {
        int mrow0 = mt * 128 + wm + i * 16 + (lane >> 2);
        int mrow1 = mrow0 + 8;
        int t0 = mrow0 >> 6, bb0 = mrow0 & 63;
        int t1 = mrow1 >> 6, bb1 = mrow1 & 63;
        float* orow0 = out + (size_t)bb0 * (TYy * Vv) + (size_t)t0 * Vv;
        float* orow1 = out + (size_t)bb1 * (TYy * Vv) + (size_t)t1 * Vv;
#pragma unroll
        for (int j = 0; j < 8; j++) {
            int ncol = nt * 128 + wn + j * 8 + (lane & 3) * 2;
            int p = ncol >> 1;
            float be = b_mo[p], bo = b_mo[Vv + p];
            orow0[p] = fmaxf(acc[i][j][0] + be, acc[i][j][1] + bo);
            orow1[p] = fmaxf(acc[i][j][2] + be, acc[i][j][3] + bo);
        }
    }
}

// ---------------------------------------------------------------------------
extern "C" void kernel_launch(void* const* d_in, const int* in_sizes, int n_in,
                              void* d_out, int out_size)
{
    const int*   y    = (const int*)d_in[0];
    const float* h_j  = (const float*)d_in[1];
    const float* emb  = (const float*)d_in[2];
    const float* W_ih = (const float*)d_in[3];
    const float* W_hh = (const float*)d_in[4];
    const float* b_ih = (const float*)d_in[5];
    const float* b_hh = (const float*)d_in[6];
    const float* W_a  = (const float*)d_in[7];
    const float* v_a  = (const float*)d_in[8];
    const float* W_mo = (const float*)d_in[9];
    const float* b_mo = (const float*)d_in[10];
    float* out = (float*)d_out;

    void* hjp_v; cudaGetSymbolAddress(&hjp_v, g_hjproj);
    float* hjp = (float*)hjp_v;

    const int smem_bytes = NSTAGE * STAGE_BYTES + 128;
    cudaFuncSetAttribute(gemm_mma_kernel,
                         cudaFuncAttributeMaxDynamicSharedMemorySize, smem_bytes);
    const int recur_smem = 15360 * 4;   // 61,440 B
    cudaFuncSetAttribute(recur_kernel,
                         cudaFuncAttributeMaxDynamicSharedMemorySize, recur_smem);

    // W_mo -> fp16 split tiles (independent of recurrence)
    conv_W_kernel<<<dim3(NKB, 500), 128>>>(W_mo);

    // hj_proj: (B*TX, 512) @ W_a[:,256:768]^T
    sgemm_nt<<<dim3((Bb * TXx) / 128, Hh / 128), 256>>>(
        Bb * TXx, Hh, 2 * Hh, h_j, 2 * Hh, W_a + Hh, 3 * Hh, hjp);

    emb_gemm_kernel<<<(TYy * Bb) / 16, 256>>>(y, emb, W_ih, b_ih);

    // persistent recurrence (barrier counter reset first, every replay)
    reset_bar_kernel<<<1, 1>>>();
    recur_kernel<<<RB, 256, recur_smem>>>(h_j, W_ih, W_hh, b_hh, W_a, v_a);

    // S -> fp16 hi tiles, then HMMA GEMM with fused max epilogue
    conv_S_kernel<<<dim3(NKA, 32), 128>>>();
    gemm_mma_kernel<<<dim3(32, 500), 256, smem_bytes>>>(out, b_mo);
}

// round 17
// speedup vs baseline: 3.7465x; 1.0639x over previous
#include <cuda_runtime.h>
#include <cuda_fp16.h>
#include <math.h>
#include <stdint.h>

#define Vv 32000
#define Ee 128
#define Hh 256
#define Bb 64
#define TYy 64
#define TXx 128

#define NKB 24             // B K-blocks of 64 fp16: [Whi|Wlo], K_eff=1536
#define NKA 12             // distinct A K-blocks (A halves identical)
#define KTILE_BYTES 16384  // 128 rows x 64 fp16 (swizzled)
#define STAGE_BYTES 32768  // A tile + B tile
#define NSTAGE 3
#define RB 128             // recurrence blocks
#define NMT 32
#define NNT 500
#define NTILES (NMT * NNT)
#define GRID_ALL 296       // 148 SMs x occupancy 2
#define DYN_SMEM 98432     // 3*32768 + align slack

// Scratch (device globals — no allocation allowed)
__device__ float g_hjproj[Bb * TXx * Hh];
__device__ float g_gi_emb[TYy * Bb * 768];
__device__ float g_S[TYy * Bb * 768];   // [t][b]{ s_i(256), c_new(512) }
__device__ unsigned g_bar_ctr;
__device__ unsigned g_progress;         // rows converted to g_A2 (64 per step)
__device__ unsigned g_tile_ctr;         // GEMM tile work queue
// fp16-split tiled operands for the big GEMM (pre-swizzled 128x64 tiles)
__device__ __align__(128) unsigned short g_A2[NMT * NKA * 8192];
__device__ __align__(128) unsigned short g_B2[NNT * NKB * 8192];

__device__ __forceinline__ float tanh_fast(float x) {
    float y; asm("tanh.approx.f32 %0, %1;" : "=f"(y) : "f"(x)); return y;
}
__device__ __forceinline__ uint32_t smem_u32(const void* p) {
    uint32_t a;
    asm("{ .reg .u64 t; cvta.to.shared.u64 t, %1; cvt.u32.u64 %0, t; }" : "=r"(a) : "l"(p));
    return a;
}
__device__ __forceinline__ uint32_t sw128(uint32_t off) { return off ^ ((off >> 3) & 0x70); }

__device__ __forceinline__ void cp_async16(uint32_t saddr, const void* g) {
    asm volatile("cp.async.cg.shared.global [%0], [%1], 16;" :: "r"(saddr), "l"(g));
}
__device__ __forceinline__ void cp_commit() { asm volatile("cp.async.commit_group;"); }

__device__ __forceinline__ void ldsm4(uint32_t* r, uint32_t addr) {
    asm volatile("ldmatrix.sync.aligned.m8n8.x4.shared.b16 {%0,%1,%2,%3}, [%4];"
                 : "=r"(r[0]), "=r"(r[1]), "=r"(r[2]), "=r"(r[3]) : "r"(addr));
}
__device__ __forceinline__ void mma16816(float* d, const uint32_t* a, uint32_t b0, uint32_t b1) {
    asm volatile("mma.sync.aligned.m16n8k16.row.col.f32.f16.f16.f32 "
                 "{%0,%1,%2,%3}, {%4,%5,%6,%7}, {%8,%9}, {%0,%1,%2,%3};"
                 : "+f"(d[0]), "+f"(d[1]), "+f"(d[2]), "+f"(d[3])
                 : "r"(a[0]), "r"(a[1]), "r"(a[2]), "r"(a[3]), "r"(b0), "r"(b1));
}

__global__ void reset_bar_kernel() { g_bar_ctr = 0; g_progress = 0; g_tile_ctr = 0; }

__device__ __forceinline__ void grid_bar(unsigned target) {
    __syncthreads();
    if (threadIdx.x == 0) {
        __threadfence();
        atomicAdd(&g_bar_ctr, 1u);
        while (*(volatile unsigned*)&g_bar_ctr < target) __nanosleep(32);
        __threadfence();
    }
    __syncthreads();
}

// ---------------------------------------------------------------------------
// K1: gi_emb = b_ih + emb_eff[y] @ W_ih[:, :128].T
// ---------------------------------------------------------------------------
__global__ __launch_bounds__(256) void emb_gemm_kernel(
    const int* __restrict__ y, const float* __restrict__ emb,
    const float* __restrict__ W_ih, const float* __restrict__ b_ih)
{
    __shared__ float Xs[16][128];
    const int tid = threadIdx.x;
    const int m_base = blockIdx.x * 16;

    for (int idx = tid; idx < 16 * 128; idx += 256) {
        int i = idx >> 7, k = idx & 127;
        int m = m_base + i;
        int tt = m >> 6, bb = m & 63;
        int yv = y[bb * TYy + tt];
        Xs[i][k] = (yv == 0) ? 0.f : emb[(size_t)yv * Ee + k];
    }
    __syncthreads();

    float acc0[16], acc1[16], acc2[16];
#pragma unroll
    for (int i = 0; i < 16; i++) { acc0[i] = 0.f; acc1[i] = 0.f; acc2[i] = 0.f; }

    const float* w0 = W_ih + (size_t)tid * 640;
    const float* w1 = W_ih + (size_t)(tid + 256) * 640;
    const float* w2 = W_ih + (size_t)(tid + 512) * 640;

    for (int k = 0; k < 128; k++) {
        float a = w0[k], b = w1[k], c = w2[k];
#pragma unroll
        for (int i = 0; i < 16; i++) {
            float x = Xs[i][k];
            acc0[i] = fmaf(x, a, acc0[i]);
            acc1[i] = fmaf(x, b, acc1[i]);
            acc2[i] = fmaf(x, c, acc2[i]);
        }
    }
    float bi0 = b_ih[tid], bi1 = b_ih[tid + 256], bi2 = b_ih[tid + 512];
#pragma unroll
    for (int i = 0; i < 16; i++) {
        size_t base = (size_t)(m_base + i) * 768;
        g_gi_emb[base + tid]       = acc0[i] + bi0;
        g_gi_emb[base + tid + 256] = acc1[i] + bi1;
        g_gi_emb[base + tid + 512] = acc2[i] + bi2;
    }
}

// ---------------------------------------------------------------------------
// fp32 SIMT SGEMM (only for hj_proj)
// ---------------------------------------------------------------------------
__global__ __launch_bounds__(256) void sgemm_nt(
    int M, int N, int K,
    const float* __restrict__ A, int lda,
    const float* __restrict__ B, int ldb,
    float* __restrict__ C)
{
    constexpr int BMs = 128, BNs = 128, BKs = 16;
    __shared__ float As[2][BKs][BMs];
    __shared__ float Bs[2][BKs][BNs];

    const int tid = threadIdx.x;
    const int m0 = blockIdx.x * BMs;
    const int n0 = blockIdx.y * BNs;
    const int tx = tid & 15;
    const int ty = tid >> 4;
    const int lRow = tid >> 1;
    const int lK = (tid & 1) * 8;

    const float* Aptr = A + (size_t)(m0 + lRow) * lda + lK;
    const float* Bptr = B + (size_t)(n0 + lRow) * ldb + lK;

    float acc[8][8];
#pragma unroll
    for (int i = 0; i < 8; i++)
#pragma unroll
        for (int j = 0; j < 8; j++) acc[i][j] = 0.f;

    const int nk = K / BKs;
    float4 ar0, ar1, br0, br1;
    ar0 = *(const float4*)(Aptr);
    ar1 = *(const float4*)(Aptr + 4);
    br0 = *(const float4*)(Bptr);
    br1 = *(const float4*)(Bptr + 4);
#pragma unroll
    for (int q = 0; q < 4; q++) {
        As[0][lK + q][lRow] = ((const float*)&ar0)[q];
        As[0][lK + 4 + q][lRow] = ((const float*)&ar1)[q];
        Bs[0][lK + q][lRow] = ((const float*)&br0)[q];
        Bs[0][lK + 4 + q][lRow] = ((const float*)&br1)[q];
    }
    __syncthreads();

    for (int kt = 0; kt < nk; kt++) {
        const int cur = kt & 1;
        const bool has_next = (kt + 1 < nk);
        if (has_next) {
            const float* Ap = Aptr + (kt + 1) * BKs;
            const float* Bp = Bptr + (kt + 1) * BKs;
            ar0 = *(const float4*)(Ap);
            ar1 = *(const float4*)(Ap + 4);
            br0 = *(const float4*)(Bp);
            br1 = *(const float4*)(Bp + 4);
        }
#pragma unroll
        for (int kk = 0; kk < BKs; kk++) {
            float4 a0 = *(const float4*)&As[cur][kk][ty * 8];
            float4 a1 = *(const float4*)&As[cur][kk][ty * 8 + 4];
            float4 b0 = *(const float4*)&Bs[cur][kk][tx * 8];
            float4 b1 = *(const float4*)&Bs[cur][kk][tx * 8 + 4];
            float av[8] = {a0.x, a0.y, a0.z, a0.w, a1.x, a1.y, a1.z, a1.w};
            float bv[8] = {b0.x, b0.y, b0.z, b0.w, b1.x, b1.y, b1.z, b1.w};
#pragma unroll
            for (int i = 0; i < 8; i++)
#pragma unroll
                for (int j = 0; j < 8; j++)
                    acc[i][j] = fmaf(av[i], bv[j], acc[i][j]);
        }
        if (has_next) {
            const int nxt = cur ^ 1;
#pragma unroll
            for (int q = 0; q < 4; q++) {
                As[nxt][lK + q][lRow] = ((const float*)&ar0)[q];
                As[nxt][lK + 4 + q][lRow] = ((const float*)&ar1)[q];
                Bs[nxt][lK + q][lRow] = ((const float*)&br0)[q];
                Bs[nxt][lK + 4 + q][lRow] = ((const float*)&br1)[q];
            }
            __syncthreads();
        }
    }
#pragma unroll
    for (int i = 0; i < 8; i++) {
        float* crow = C + (size_t)(m0 + ty * 8 + i) * N + n0 + tx * 8;
        float4 v0 = {acc[i][0], acc[i][1], acc[i][2], acc[i][3]};
        float4 v1 = {acc[i][4], acc[i][5], acc[i][6], acc[i][7]};
        *(float4*)(crow) = v0;
        *(float4*)(crow + 4) = v1;
    }
}

// ---------------------------------------------------------------------------
// conv_W: W_mo (fp32, interleave-reordered rows) -> g_B2 fp16 split tiles.
// ---------------------------------------------------------------------------
__global__ __launch_bounds__(128) void conv_W_kernel(const float* __restrict__ W_mo)
{
    const int kb = blockIdx.x, nt = blockIdx.y;
    const int r = threadIdx.x;
    const int n = nt * 128 + r;
    const int wrow = (n & 1) * Vv + (n >> 1);
    const int term = kb / 12;
    const int kk0 = (kb % 12) * 64;
    const float* src = W_mo + (size_t)wrow * 768 + kk0;
    char* tile = (char*)g_B2 + (size_t)(nt * NKB + kb) * KTILE_BYTES;

#pragma unroll
    for (int j = 0; j < 8; j++) {
        float4 x0 = *(const float4*)(src + j * 8);
        float4 x1 = *(const float4*)(src + j * 8 + 4);
        float xs[8] = {x0.x, x0.y, x0.z, x0.w, x1.x, x1.y, x1.z, x1.w};
        unsigned short o[8];
#pragma unroll
        for (int q = 0; q < 8; q++) {
            __half h = __float2half_rn(xs[q]);
            if (term == 1) h = __float2half_rn(xs[q] - __half2float(h));
            o[q] = *(unsigned short*)&h;
        }
        uint32_t off = sw128((uint32_t)r * 128 + j * 16);
        *(uint4*)(tile + off) = *(uint4*)o;
    }
}

// ---------------------------------------------------------------------------
// One GEMM tile (mt, nt): 128x128x(NKB*64) fp16 HMMA, 3-stage cp.async,
// fused pair-max + bias epilogue. A K-blocks repeat (kb % NKA).
// ---------------------------------------------------------------------------
__device__ void gemm_tile(uint32_t sbase, int mt, int nt,
                          float* __restrict__ out, const float* __restrict__ b_mo)
{
    const int tid = threadIdx.x;
    const int lane = tid & 31;
    const int wid = tid >> 5;
    const int wm = (wid & 3) * 32;
    const int wn = (wid >> 2) * 64;

    const char* Ab = (const char*)g_A2 + (size_t)mt * NKA * KTILE_BYTES;
    const char* Bbp = (const char*)g_B2 + (size_t)nt * NKB * KTILE_BYTES;

    auto load_stage = [&](int kb, int s) {
        uint32_t sa = sbase + s * STAGE_BYTES + tid * 16;
        const char* ga = Ab + (size_t)(kb % NKA) * KTILE_BYTES + tid * 16;
        const char* gb = Bbp + (size_t)kb * KTILE_BYTES + tid * 16;
#pragma unroll
        for (int i = 0; i < 4; i++) cp_async16(sa + i * 4096, ga + i * 4096);
        sa += 16384;
#pragma unroll
        for (int i = 0; i < 4; i++) cp_async16(sa + i * 4096, gb + i * 4096);
        cp_commit();
    };

    float acc[2][8][4];
#pragma unroll
    for (int i = 0; i < 2; i++)
#pragma unroll
        for (int j = 0; j < 8; j++)
#pragma unroll
            for (int q = 0; q < 4; q++) acc[i][j][q] = 0.f;

    load_stage(0, 0);
    load_stage(1, 1);

    const uint32_t a_row = wm + (lane & 15);
    const uint32_t a_kb  = (lane >> 4) * 16;
    const uint32_t b_row = wn + (lane & 7) + ((lane >> 4) << 3);
    const uint32_t b_kb  = ((lane >> 3) & 1) * 16;

    for (int kb = 0; kb < NKB; kb++) {
        const int s = kb % NSTAGE;
        if (kb >= NKB - 1) asm volatile("cp.async.wait_group 0;" ::: "memory");
        else               asm volatile("cp.async.wait_group 1;" ::: "memory");
        __syncthreads();

        const uint32_t abase = sbase + s * STAGE_BYTES;
        const uint32_t bbase = abase + 16384;

#pragma unroll
        for (int ks = 0; ks < 4; ks++) {
            uint32_t afr[2][4];
#pragma unroll
            for (int i = 0; i < 2; i++) {
                uint32_t ad = abase + sw128((a_row + i * 16) * 128 + ks * 32 + a_kb);
                ldsm4(afr[i], ad);
            }
            uint32_t bfr[4][4];
#pragma unroll
            for (int j = 0; j < 4; j++) {
                uint32_t bd = bbase + sw128((b_row + j * 16) * 128 + ks * 32 + b_kb);
                ldsm4(bfr[j], bd);
            }
#pragma unroll
            for (int i = 0; i < 2; i++)
#pragma unroll
                for (int j = 0; j < 8; j++) {
                    uint32_t b0 = bfr[j >> 1][(j & 1) * 2];
                    uint32_t b1 = bfr[j >> 1][(j & 1) * 2 + 1];
                    mma16816(acc[i][j], afr[i], b0, b1);
                }
        }

        const int nxt = kb + 2;
        if (nxt < NKB) load_stage(nxt, nxt % NSTAGE);
    }

#pragma unroll
    for (int i = 0; i < 2; i++) {
        int mrow0 = mt * 128 + wm + i * 16 + (lane >> 2);
        int mrow1 = mrow0 + 8;
        int t0 = mrow0 >> 6, bb0 = mrow0 & 63;
        int t1 = mrow1 >> 6, bb1 = mrow1 & 63;
        float* orow0 = out + (size_t)bb0 * (TYy * Vv) + (size_t)t0 * Vv;
        float* orow1 = out + (size_t)bb1 * (TYy * Vv) + (size_t)t1 * Vv;
#pragma unroll
        for (int j = 0; j < 8; j++) {
            int ncol = nt * 128 + wn + j * 8 + (lane & 3) * 2;
            int p = ncol >> 1;
            float be = b_mo[p], bo = b_mo[Vv + p];
            orow0[p] = fmaxf(acc[i][j][0] + be, acc[i][j][1] + bo);
            orow1[p] = fmaxf(acc[i][j][2] + be, acc[i][j][3] + bo);
        }
    }
}

// ---------------------------------------------------------------------------
// Recurrence role (blocks 0..RB-1). Same as R14 recur_kernel, plus: attn
// blocks (0..63) convert their finished row [s_i|c_new] into g_A2 fp16
// (swizzled) and bump g_progress.
// ---------------------------------------------------------------------------
__device__ void recur_role(
    float* sm, int blk,
    const float* __restrict__ h_j, const float* __restrict__ W_ih,
    const float* __restrict__ W_hh, const float* __restrict__ b_hh,
    const float* __restrict__ W_a, const float* __restrict__ v_a)
{
    float* Wk   = sm;              // [768][8]
    float* Xs   = sm + 6144;       // [2][64][64]
    float* si_s = sm + 14336;
    float* sp_s = si_s + 256;
    float* va_s = sp_s + 256;
    float* e_s  = va_s + 256;
    float* red_s = e_s + 128;
    float* row_s = red_s + 128;    // [768]

    const int tid = threadIdx.x;
    const int bg = tid & 15, ks = tid >> 4;
    const int wid = tid >> 5, lane = tid & 31;
    const int lb = tid & 63, lq = tid >> 6;

    for (int r = 0; r < 6; r++) {
        int g = r >> 1, i = r & 1;
        int row = g * 256 + blk * 2 + i;
        const float* wih = W_ih + (size_t)row * 640 + 128;
        const float* whh = W_hh + (size_t)row * 256;
        for (int k = tid; k < 768; k += 256)
            Wk[k * 8 + r] = (k < 512) ? wih[k] : whh[k - 512];
    }
    for (int k = tid; k < 768; k += 256) { Wk[k * 8 + 6] = 0.f; Wk[k * 8 + 7] = 0.f; }
    va_s[tid] = v_a[tid];

    unsigned bar_target = 0;

    for (int t = 0; t < TYy; t++) {
        const float* Sprev = g_S + (size_t)(t - 1) * Bb * 768;

        float acc[4][6], anc[4][2];
#pragma unroll
        for (int a = 0; a < 4; a++) {
#pragma unroll
            for (int r = 0; r < 6; r++) acc[a][r] = 0.f;
            anc[a][0] = 0.f; anc[a][1] = 0.f;
        }

        if (t > 0) {
            const float* srow = Sprev + (size_t)lb * 768;
#pragma unroll
            for (int j = 0; j < 4; j++) {
                int kl = lq * 16 + j * 4;
                float4 v = *(const float4*)(srow + 256 + kl);
                float* dst = Xs + kl * 64 + lb;
                dst[0] = v.x; dst[64] = v.y; dst[128] = v.z; dst[192] = v.w;
            }
            for (int c = 0; c < 12; c++) {
                __syncthreads();
                float4 pf[4];
                if (c < 11) {
                    int cn = c + 1;
                    int base = (cn < 8) ? (256 + cn * 64) : (cn * 64 - 512);
#pragma unroll
                    for (int j = 0; j < 4; j++)
                        pf[j] = *(const float4*)(srow + base + lq * 16 + j * 4);
                }
                const float* XB = Xs + (c & 1) * 4096;
#pragma unroll
                for (int kq = 0; kq < 4; kq++) {
                    int kl = ks * 4 + kq;
                    int kg = c * 64 + kl;
                    float4 xv = *(const float4*)(XB + kl * 64 + bg * 4);
                    float4 w0 = *(const float4*)(Wk + kg * 8);
                    float4 w1 = *(const float4*)(Wk + kg * 8 + 4);
                    float xb[4] = {xv.x, xv.y, xv.z, xv.w};
#pragma unroll
                    for (int a = 0; a < 4; a++) {
                        acc[a][0] = fmaf(xb[a], w0.x, acc[a][0]);
                        acc[a][1] = fmaf(xb[a], w0.y, acc[a][1]);
                        acc[a][2] = fmaf(xb[a], w0.z, acc[a][2]);
                        acc[a][3] = fmaf(xb[a], w0.w, acc[a][3]);
                        acc[a][4] = fmaf(xb[a], w1.x, acc[a][4]);
                        acc[a][5] = fmaf(xb[a], w1.y, acc[a][5]);
                    }
                }
                if (c == 7) {
#pragma unroll
                    for (int a = 0; a < 4; a++) {
                        anc[a][0] = acc[a][4]; anc[a][1] = acc[a][5];
                        acc[a][4] = 0.f; acc[a][5] = 0.f;
                    }
                }
                if (c < 11) {
                    float* dst0 = Xs + ((c + 1) & 1) * 4096;
#pragma unroll
                    for (int j = 0; j < 4; j++) {
                        int kl = lq * 16 + j * 4;
                        float* dst = dst0 + kl * 64 + lb;
                        dst[0] = pf[j].x; dst[64] = pf[j].y;
                        dst[128] = pf[j].z; dst[192] = pf[j].w;
                    }
                }
            }
        }
        __syncthreads();

        {
            float vals[32];
#pragma unroll
            for (int a = 0; a < 4; a++) {
                vals[a*8+0] = acc[a][0]; vals[a*8+1] = acc[a][1];
                vals[a*8+2] = acc[a][2]; vals[a*8+3] = acc[a][3];
                vals[a*8+4] = acc[a][4]; vals[a*8+5] = acc[a][5];
                vals[a*8+6] = anc[a][0]; vals[a*8+7] = anc[a][1];
            }
#pragma unroll
            for (int v = 0; v < 32; v++)
                vals[v] += __shfl_down_sync(0xffffffffu, vals[v], 16);
            if (lane < 16) {
                float* pr = Xs + (wid * 16 + lane) * 32;
#pragma unroll
                for (int v = 0; v < 32; v += 4) {
                    float4 w = {vals[v], vals[v+1], vals[v+2], vals[v+3]};
                    *(float4*)(pr + v) = w;
                }
            }
        }
        __syncthreads();

        if (tid < 128) {
            int b = tid & 63, i = tid >> 6;
            int bgr = b >> 2, bp = b & 3;
            float ar = 0.f, az = 0.f, anh = 0.f, ancv = 0.f;
#pragma unroll
            for (int w = 0; w < 8; w++) {
                const float* p = Xs + (w * 16 + bgr) * 32 + bp * 8;
                ar += p[0 + i]; az += p[2 + i]; anh += p[4 + i]; ancv += p[6 + i];
            }
            int u = blk * 2 + i;
            const float* gi = g_gi_emb + ((size_t)t * Bb + b) * 768;
            float gr = ar + gi[u] + b_hh[u];
            float gz = az + gi[256 + u] + b_hh[256 + u];
            float hn = anh + b_hh[512 + u];
            float gn = ancv + gi[512 + u];
            float r = 1.f / (1.f + expf(-gr));
            float z = 1.f / (1.f + expf(-gz));
            float n = tanhf(gn + r * hn);
            float hp = (t > 0) ? Sprev[(size_t)b * 768 + u] : 0.f;
            g_S[((size_t)t * Bb + b) * 768 + u] = (1.f - z) * n + z * hp;
        }

        bar_target += RB; grid_bar(bar_target);

        if (blk < 64) {
            const int b = blk;
            const size_t gbase = ((size_t)t * Bb + b) * 768;
            si_s[tid] = g_S[gbase + tid];
            __syncthreads();
            {
                float sp = 0.f;
                const float4* wa = (const float4*)(W_a + (size_t)tid * 768);
                const float4* sip = (const float4*)si_s;
#pragma unroll 8
                for (int k4 = 0; k4 < 64; k4++) {
                    float4 sv = sip[k4]; float4 w = wa[k4];
                    sp += sv.x * w.x + sv.y * w.y + sv.z * w.z + sv.w * w.w;
                }
                sp_s[tid] = sp;
            }
            __syncthreads();
            if (tid < 128) {
                const float4* hp = (const float4*)(g_hjproj + ((size_t)b * TXx + tid) * Hh);
                const float4* spv = (const float4*)sp_s;
                const float4* vav = (const float4*)va_s;
                float e = 0.f;
#pragma unroll 4
                for (int h4 = 0; h4 < 64; h4++) {
                    float4 h = hp[h4]; float4 s = spv[h4]; float4 v = vav[h4];
                    e += tanh_fast(s.x + h.x) * v.x;
                    e += tanh_fast(s.y + h.y) * v.y;
                    e += tanh_fast(s.z + h.z) * v.z;
                    e += tanh_fast(s.w + h.w) * v.w;
                }
                e_s[tid] = e; red_s[tid] = e;
            }
            __syncthreads();
            for (int st = 64; st > 0; st >>= 1) {
                if (tid < st) red_s[tid] = fmaxf(red_s[tid], red_s[tid + st]);
                __syncthreads();
            }
            float mx = red_s[0];
            __syncthreads();
            if (tid < 128) { float ex = expf(e_s[tid] - mx); e_s[tid] = ex; red_s[tid] = ex; }
            __syncthreads();
            for (int st = 64; st > 0; st >>= 1) {
                if (tid < st) red_s[tid] += red_s[tid + st];
                __syncthreads();
            }
            float inv = 1.f / red_s[0];
            __syncthreads();
            if (tid < 128) e_s[tid] *= inv;
            __syncthreads();

            float c0 = 0.f, c1 = 0.f;
            const float* hjb = h_j + (size_t)b * TXx * 512;
#pragma unroll 8
            for (int tp = 0; tp < 128; tp++) {
                float al = e_s[tp];
                c0 = fmaf(al, hjb[(size_t)tp * 512 + tid], c0);
                c1 = fmaf(al, hjb[(size_t)tp * 512 + 256 + tid], c1);
            }
            g_S[gbase + 256 + tid] = c0;
            g_S[gbase + 512 + tid] = c1;

            // stage full row [s|c0|c1] and convert into g_A2 (fp16, swizzled)
            row_s[tid] = si_s[tid];
            row_s[256 + tid] = c0;
            row_s[512 + tid] = c1;
            __syncthreads();
            if (tid < 96) {
                int kb = tid >> 3, jj = tid & 7;
                int m = t * 64 + b;
                int mt_ = m >> 7, r_ = m & 127;
                const float* srcp = row_s + kb * 64 + jj * 8;
                unsigned short o[8];
#pragma unroll
                for (int q = 0; q < 8; q++) {
                    __half h = __float2half_rn(srcp[q]);
                    o[q] = *(unsigned short*)&h;
                }
                char* tilep = (char*)g_A2 + (size_t)(mt_ * NKA + kb) * KTILE_BYTES;
                *(uint4*)(tilep + sw128((uint32_t)r_ * 128 + jj * 16)) = *(uint4*)o;
            }
            __threadfence();
            __syncthreads();
            if (tid == 0) atomicAdd(&g_progress, 1u);
        }
        bar_target += RB; grid_bar(bar_target);
    }
}

// ---------------------------------------------------------------------------
// Mega-kernel: blocks 0..RB-1 run the recurrence, then everyone drains the
// GEMM tile queue (mt-major order; tile waits for its m-tile's rows).
// ---------------------------------------------------------------------------
__global__ __launch_bounds__(256, 2) void mega_kernel(
    float* __restrict__ out,
    const float* __restrict__ h_j, const float* __restrict__ W_ih,
    const float* __restrict__ W_hh, const float* __restrict__ b_hh,
    const float* __restrict__ W_a, const float* __restrict__ v_a,
    const float* __restrict__ b_mo)
{
    extern __shared__ float sm[];
    __shared__ int s_tile;
    const int tid = threadIdx.x;
    const int blk = blockIdx.x;

    if (blk < RB)
        recur_role(sm, blk, h_j, W_ih, W_hh, b_hh, W_a, v_a);

    const uint32_t sbase = (smem_u32(sm) + 127) & ~127u;

    for (;;) {
        if (tid == 0) s_tile = (int)atomicAdd(&g_tile_ctr, 1u);
        __syncthreads();
        int tile = s_tile;
        if (tile >= NTILES) break;
        int mt = tile / NNT, nt = tile % NNT;
        if (tid == 0) {
            unsigned need = 64u * (unsigned)(2 * mt + 2);
            while (*(volatile unsigned*)&g_progress < need) __nanosleep(256);
            __threadfence();
        }
        __syncthreads();
        gemm_tile(sbase, mt, nt, out, b_mo);
        __syncthreads();
    }
}

// ---------------------------------------------------------------------------
extern "C" void kernel_launch(void* const* d_in, const int* in_sizes, int n_in,
                              void* d_out, int out_size)
{
    const int*   y    = (const int*)d_in[0];
    const float* h_j  = (const float*)d_in[1];
    const float* emb  = (const float*)d_in[2];
    const float* W_ih = (const float*)d_in[3];
    const float* W_hh = (const float*)d_in[4];
    const float* b_ih = (const float*)d_in[5];
    const float* b_hh = (const float*)d_in[6];
    const float* W_a  = (const float*)d_in[7];
    const float* v_a  = (const float*)d_in[8];
    const float* W_mo = (const float*)d_in[9];
    const float* b_mo = (const float*)d_in[10];
    float* out = (float*)d_out;

    void* hjp_v; cudaGetSymbolAddress(&hjp_v, g_hjproj);
    float* hjp = (float*)hjp_v;

    cudaFuncSetAttribute(mega_kernel,
                         cudaFuncAttributeMaxDynamicSharedMemorySize, DYN_SMEM);

    // W_mo -> fp16 split tiles (independent of recurrence)
    conv_W_kernel<<<dim3(NKB, 500), 128>>>(W_mo);

    // hj_proj: (B*TX, 512) @ W_a[:,256:768]^T
    sgemm_nt<<<dim3((Bb * TXx) / 128, Hh / 128), 256>>>(
        Bb * TXx, Hh, 2 * Hh, h_j, 2 * Hh, W_a + Hh, 3 * Hh, hjp);

    emb_gemm_kernel<<<(TYy * Bb) / 16, 256>>>(y, emb, W_ih, b_ih);

    // counters reset every replay, then the fused recurrence+GEMM kernel
    reset_bar_kernel<<<1, 1>>>();
    mega_kernel<<<GRID_ALL, 256, DYN_SMEM>>>(out, h_j, W_ih, W_hh, b_hh,
                                             W_a, v_a, b_mo);
}